// round 1
// baseline (speedup 1.0000x reference)
#include <cuda_runtime.h>

#define NHEADS 16
#define HDIM   64
#define EMBED  1024
#define BATCH  2
#define SEQ    2048
#define MTOT   (BATCH*SEQ)          // 4096
#define QKVN   (3*EMBED)            // 3072

// Scratch (static device globals — no allocations allowed)
__device__ float g_q[BATCH*NHEADS*SEQ*HDIM];     // [B,H,S,d]
__device__ float g_k[BATCH*NHEADS*SEQ*HDIM];
__device__ float g_v[BATCH*NHEADS*SEQ*HDIM];
__device__ float g_attn[BATCH*SEQ*EMBED];        // [B,S,E]

// ---------------------------------------------------------------------------
// QKV projection: qkv[m, n] = dot(x[m,:], qkv_w[n,:]) + qkv_b[n]
// Scatter epilogue into g_q/g_k/g_v with [B,H,S,d] layout.
// n -> head = n/192, type = (n%192)/64, dim = n%64
// ---------------------------------------------------------------------------
__global__ __launch_bounds__(256) void qkv_gemm_kernel(
    const float* __restrict__ X, const float* __restrict__ W,
    const float* __restrict__ bias)
{
    __shared__ float As[16][128];
    __shared__ float Bs[16][128];
    const int tid = threadIdx.x;
    const int tx  = tid & 15;
    const int ty  = tid >> 4;
    const int rowBase = blockIdx.y * 128;
    const int colBase = blockIdx.x * 128;
    const int lr = tid >> 2;   // 0..63
    const int lc = tid & 3;    // 0..3

    float acc[8][8];
    #pragma unroll
    for (int i = 0; i < 8; i++)
        #pragma unroll
        for (int j = 0; j < 8; j++) acc[i][j] = 0.f;

    for (int k0 = 0; k0 < EMBED; k0 += 16) {
        #pragma unroll
        for (int p = 0; p < 2; p++) {
            const int r = lr + p*64;
            float4 va = *(const float4*)(X + (size_t)(rowBase + r)*EMBED + k0 + lc*4);
            As[lc*4+0][r] = va.x; As[lc*4+1][r] = va.y;
            As[lc*4+2][r] = va.z; As[lc*4+3][r] = va.w;
            float4 vb = *(const float4*)(W + (size_t)(colBase + r)*EMBED + k0 + lc*4);
            Bs[lc*4+0][r] = vb.x; Bs[lc*4+1][r] = vb.y;
            Bs[lc*4+2][r] = vb.z; Bs[lc*4+3][r] = vb.w;
        }
        __syncthreads();
        #pragma unroll
        for (int k = 0; k < 16; k++) {
            float a[8], b[8];
            *(float4*)&a[0] = *(const float4*)&As[k][ty*8];
            *(float4*)&a[4] = *(const float4*)&As[k][ty*8+4];
            *(float4*)&b[0] = *(const float4*)&Bs[k][tx*8];
            *(float4*)&b[4] = *(const float4*)&Bs[k][tx*8+4];
            #pragma unroll
            for (int i = 0; i < 8; i++)
                #pragma unroll
                for (int j = 0; j < 8; j++) acc[i][j] += a[i]*b[j];
        }
        __syncthreads();
    }

    #pragma unroll
    for (int i = 0; i < 8; i++) {
        const int orow = rowBase + ty*8 + i;
        const int b_ = orow >> 11;            // /2048
        const int s_ = orow & (SEQ-1);
        #pragma unroll
        for (int j = 0; j < 8; j++) {
            const int oc = colBase + tx*8 + j;
            const float v = acc[i][j] + bias[oc];
            const int head = oc / 192;
            const int rem  = oc - head*192;
            const int t    = rem >> 6;
            const int dim  = rem & 63;
            const size_t dst = ((size_t)(b_*NHEADS + head)*SEQ + s_)*HDIM + dim;
            float* buf = (t == 0) ? g_q : (t == 1) ? g_k : g_v;
            buf[dst] = v;
        }
    }
}

// ---------------------------------------------------------------------------
// Flash attention fp32: per CTA one (b, h, 64-query tile). Online softmax.
// smem: Qs[64][64] + KV[64][64] (K^T then V, reused) + Ps[64][64] = 48 KB
// 256 threads: tx=0..7 (8 cols), ty=0..31 (2 rows each)
// ---------------------------------------------------------------------------
__global__ __launch_bounds__(256) void flash_kernel()
{
    __shared__ float Qs[64][64];
    __shared__ float KV[64][64];
    __shared__ float Ps[64][64];
    const int tid = threadIdx.x;
    const int tx  = tid & 7;
    const int ty  = tid >> 3;
    const int head = blockIdx.y;
    const int bz   = blockIdx.z;
    const size_t base = (size_t)(bz*NHEADS + head)*SEQ*HDIM;
    const float* Qg = g_q + base;
    const float* Kg = g_k + base;
    const float* Vg = g_v + base;
    const int q0 = blockIdx.x * 64;
    const int qr0 = ty*2;

    // Load Q tile [64 q][64 d], natural layout (coalesced, conflict-free)
    #pragma unroll
    for (int p = 0; p < 4; p++) {
        const int idx = tid + p*256;
        const int r = idx >> 4, c4 = idx & 15;
        *(float4*)&Qs[r][c4*4] = *(const float4*)(Qg + (size_t)(q0 + r)*HDIM + c4*4);
    }

    float m_i[2] = {-1e30f, -1e30f};
    float l_i[2] = {0.f, 0.f};
    float o[2][8];
    #pragma unroll
    for (int j = 0; j < 8; j++) { o[0][j] = 0.f; o[1][j] = 0.f; }

    for (int kt = 0; kt < SEQ/64; kt++) {
        const int k0 = kt*64;
        __syncthreads();   // prior PV done reading KV/Ps; Q visible on iter 0
        // Load K transposed: KV[d][k]  (strided gmem read, conflict-free STS)
        #pragma unroll
        for (int p = 0; p < 4; p++) {
            const int idx = tid + p*256;
            const int c4 = idx >> 6;   // d4 0..15
            const int r  = idx & 63;   // k  0..63
            float4 v = *(const float4*)(Kg + (size_t)(k0 + r)*HDIM + c4*4);
            KV[c4*4+0][r] = v.x; KV[c4*4+1][r] = v.y;
            KV[c4*4+2][r] = v.z; KV[c4*4+3][r] = v.w;
        }
        __syncthreads();

        // S = Q K^T * 0.125  (2 rows x 8 cols per thread)
        float s0[8], s1[8];
        #pragma unroll
        for (int j = 0; j < 8; j++) { s0[j] = 0.f; s1[j] = 0.f; }
        #pragma unroll 16
        for (int d = 0; d < 64; d++) {
            const float a0 = Qs[qr0][d];
            const float a1 = Qs[qr0+1][d];
            float b[8];
            *(float4*)&b[0] = *(const float4*)&KV[d][tx*8];
            *(float4*)&b[4] = *(const float4*)&KV[d][tx*8+4];
            #pragma unroll
            for (int j = 0; j < 8; j++) { s0[j] += a0*b[j]; s1[j] += a1*b[j]; }
        }
        #pragma unroll
        for (int j = 0; j < 8; j++) { s0[j] *= 0.125f; s1[j] *= 0.125f; }

        // Row max across this thread + the 8-lane tx group
        float mx0 = s0[0], mx1 = s1[0];
        #pragma unroll
        for (int j = 1; j < 8; j++) { mx0 = fmaxf(mx0, s0[j]); mx1 = fmaxf(mx1, s1[j]); }
        #pragma unroll
        for (int off = 4; off > 0; off >>= 1) {
            mx0 = fmaxf(mx0, __shfl_xor_sync(0xffffffffu, mx0, off));
            mx1 = fmaxf(mx1, __shfl_xor_sync(0xffffffffu, mx1, off));
        }
        const float mn0 = fmaxf(m_i[0], mx0);
        const float mn1 = fmaxf(m_i[1], mx1);

        float sum0 = 0.f, sum1 = 0.f;
        #pragma unroll
        for (int j = 0; j < 8; j++) {
            s0[j] = __expf(s0[j] - mn0); sum0 += s0[j];
            s1[j] = __expf(s1[j] - mn1); sum1 += s1[j];
        }
        #pragma unroll
        for (int off = 4; off > 0; off >>= 1) {
            sum0 += __shfl_xor_sync(0xffffffffu, sum0, off);
            sum1 += __shfl_xor_sync(0xffffffffu, sum1, off);
        }
        const float f0 = __expf(m_i[0] - mn0);
        const float f1 = __expf(m_i[1] - mn1);
        l_i[0] = l_i[0]*f0 + sum0;
        l_i[1] = l_i[1]*f1 + sum1;
        m_i[0] = mn0; m_i[1] = mn1;
        #pragma unroll
        for (int j = 0; j < 8; j++) { o[0][j] *= f0; o[1][j] *= f1; }

        // Store P
        *(float4*)&Ps[qr0  ][tx*8  ] = make_float4(s0[0], s0[1], s0[2], s0[3]);
        *(float4*)&Ps[qr0  ][tx*8+4] = make_float4(s0[4], s0[5], s0[6], s0[7]);
        *(float4*)&Ps[qr0+1][tx*8  ] = make_float4(s1[0], s1[1], s1[2], s1[3]);
        *(float4*)&Ps[qr0+1][tx*8+4] = make_float4(s1[4], s1[5], s1[6], s1[7]);
        __syncthreads();   // everyone done reading K^T; Ps visible

        // Load V natural: KV[k][d]
        #pragma unroll
        for (int p = 0; p < 4; p++) {
            const int idx = tid + p*256;
            const int r = idx >> 4, c4 = idx & 15;
            *(float4*)&KV[r][c4*4] = *(const float4*)(Vg + (size_t)(k0 + r)*HDIM + c4*4);
        }
        __syncthreads();

        // O += P V
        #pragma unroll 16
        for (int k = 0; k < 64; k++) {
            const float a0 = Ps[qr0][k];
            const float a1 = Ps[qr0+1][k];
            float b[8];
            *(float4*)&b[0] = *(const float4*)&KV[k][tx*8];
            *(float4*)&b[4] = *(const float4*)&KV[k][tx*8+4];
            #pragma unroll
            for (int j = 0; j < 8; j++) { o[0][j] += a0*b[j]; o[1][j] += a1*b[j]; }
        }
    }

    const float inv0 = 1.f / l_i[0];
    const float inv1 = 1.f / l_i[1];
    #pragma unroll
    for (int j = 0; j < 8; j++) { o[0][j] *= inv0; o[1][j] *= inv1; }

    // Write to g_attn [B,S,E]
    float* dst0 = g_attn + ((size_t)bz*SEQ + q0 + qr0)*EMBED + head*HDIM + tx*8;
    float* dst1 = dst0 + EMBED;
    *(float4*)(dst0  ) = make_float4(o[0][0], o[0][1], o[0][2], o[0][3]);
    *(float4*)(dst0+4) = make_float4(o[0][4], o[0][5], o[0][6], o[0][7]);
    *(float4*)(dst1  ) = make_float4(o[1][0], o[1][1], o[1][2], o[1][3]);
    *(float4*)(dst1+4) = make_float4(o[1][4], o[1][5], o[1][6], o[1][7]);
}

// ---------------------------------------------------------------------------
// Output projection: out[m, n] = dot(g_attn[m,:], out_w[n,:]) + out_b[n]
// ---------------------------------------------------------------------------
__global__ __launch_bounds__(256) void out_gemm_kernel(
    const float* __restrict__ W, const float* __restrict__ bias,
    float* __restrict__ out)
{
    __shared__ float As[16][128];
    __shared__ float Bs[16][128];
    const int tid = threadIdx.x;
    const int tx  = tid & 15;
    const int ty  = tid >> 4;
    const int rowBase = blockIdx.y * 128;
    const int colBase = blockIdx.x * 128;
    const int lr = tid >> 2;
    const int lc = tid & 3;

    float acc[8][8];
    #pragma unroll
    for (int i = 0; i < 8; i++)
        #pragma unroll
        for (int j = 0; j < 8; j++) acc[i][j] = 0.f;

    for (int k0 = 0; k0 < EMBED; k0 += 16) {
        #pragma unroll
        for (int p = 0; p < 2; p++) {
            const int r = lr + p*64;
            float4 va = *(const float4*)(g_attn + (size_t)(rowBase + r)*EMBED + k0 + lc*4);
            As[lc*4+0][r] = va.x; As[lc*4+1][r] = va.y;
            As[lc*4+2][r] = va.z; As[lc*4+3][r] = va.w;
            float4 vb = *(const float4*)(W + (size_t)(colBase + r)*EMBED + k0 + lc*4);
            Bs[lc*4+0][r] = vb.x; Bs[lc*4+1][r] = vb.y;
            Bs[lc*4+2][r] = vb.z; Bs[lc*4+3][r] = vb.w;
        }
        __syncthreads();
        #pragma unroll
        for (int k = 0; k < 16; k++) {
            float a[8], b[8];
            *(float4*)&a[0] = *(const float4*)&As[k][ty*8];
            *(float4*)&a[4] = *(const float4*)&As[k][ty*8+4];
            *(float4*)&b[0] = *(const float4*)&Bs[k][tx*8];
            *(float4*)&b[4] = *(const float4*)&Bs[k][tx*8+4];
            #pragma unroll
            for (int i = 0; i < 8; i++)
                #pragma unroll
                for (int j = 0; j < 8; j++) acc[i][j] += a[i]*b[j];
        }
        __syncthreads();
    }

    #pragma unroll
    for (int i = 0; i < 8; i++) {
        const int orow = rowBase + ty*8 + i;
        const int oc0  = colBase + tx*8;
        float4 r0 = make_float4(acc[i][0] + bias[oc0+0], acc[i][1] + bias[oc0+1],
                                acc[i][2] + bias[oc0+2], acc[i][3] + bias[oc0+3]);
        float4 r1 = make_float4(acc[i][4] + bias[oc0+4], acc[i][5] + bias[oc0+5],
                                acc[i][6] + bias[oc0+6], acc[i][7] + bias[oc0+7]);
        *(float4*)(out + (size_t)orow*EMBED + oc0    ) = r0;
        *(float4*)(out + (size_t)orow*EMBED + oc0 + 4) = r1;
    }
}

extern "C" void kernel_launch(void* const* d_in, const int* in_sizes, int n_in,
                              void* d_out, int out_size)
{
    const float* x     = (const float*)d_in[0];
    const float* qkv_w = (const float*)d_in[1];
    const float* qkv_b = (const float*)d_in[2];
    const float* out_w = (const float*)d_in[3];
    const float* out_b = (const float*)d_in[4];
    float* out = (float*)d_out;

    qkv_gemm_kernel<<<dim3(QKVN/128, MTOT/128), 256>>>(x, qkv_w, qkv_b);
    flash_kernel<<<dim3(SEQ/64, NHEADS, BATCH), 256>>>();
    out_gemm_kernel<<<dim3(EMBED/128, MTOT/128), 256>>>(out_w, out_b, out);
}

// round 2
// speedup vs baseline: 2.7198x; 2.7198x over previous
#include <cuda_runtime.h>
#include <cuda_bf16.h>

#define NHEADS 16
#define HDIM   64
#define EMBED  1024
#define BATCH  2
#define SEQ    2048
#define MTOT   (BATCH*SEQ)          // 4096
#define QKVN   (3*EMBED)            // 3072

// Scratch (static device globals — no allocations allowed)
__device__ float g_q[BATCH*NHEADS*SEQ*HDIM];     // [B,H,S,d]
__device__ float g_k[BATCH*NHEADS*SEQ*HDIM];
__device__ float g_v[BATCH*NHEADS*SEQ*HDIM];
__device__ float g_attn[BATCH*SEQ*EMBED];        // [B,S,E]

// ---------------------------------------------------------------------------
// QKV projection (fp32 SGEMM, unchanged this round)
// ---------------------------------------------------------------------------
__global__ __launch_bounds__(256) void qkv_gemm_kernel(
    const float* __restrict__ X, const float* __restrict__ W,
    const float* __restrict__ bias)
{
    __shared__ float As[16][128];
    __shared__ float Bs[16][128];
    const int tid = threadIdx.x;
    const int tx  = tid & 15;
    const int ty  = tid >> 4;
    const int rowBase = blockIdx.y * 128;
    const int colBase = blockIdx.x * 128;
    const int lr = tid >> 2;
    const int lc = tid & 3;

    float acc[8][8];
    #pragma unroll
    for (int i = 0; i < 8; i++)
        #pragma unroll
        for (int j = 0; j < 8; j++) acc[i][j] = 0.f;

    for (int k0 = 0; k0 < EMBED; k0 += 16) {
        #pragma unroll
        for (int p = 0; p < 2; p++) {
            const int r = lr + p*64;
            float4 va = *(const float4*)(X + (size_t)(rowBase + r)*EMBED + k0 + lc*4);
            As[lc*4+0][r] = va.x; As[lc*4+1][r] = va.y;
            As[lc*4+2][r] = va.z; As[lc*4+3][r] = va.w;
            float4 vb = *(const float4*)(W + (size_t)(colBase + r)*EMBED + k0 + lc*4);
            Bs[lc*4+0][r] = vb.x; Bs[lc*4+1][r] = vb.y;
            Bs[lc*4+2][r] = vb.z; Bs[lc*4+3][r] = vb.w;
        }
        __syncthreads();
        #pragma unroll
        for (int k = 0; k < 16; k++) {
            float a[8], b[8];
            *(float4*)&a[0] = *(const float4*)&As[k][ty*8];
            *(float4*)&a[4] = *(const float4*)&As[k][ty*8+4];
            *(float4*)&b[0] = *(const float4*)&Bs[k][tx*8];
            *(float4*)&b[4] = *(const float4*)&Bs[k][tx*8+4];
            #pragma unroll
            for (int i = 0; i < 8; i++)
                #pragma unroll
                for (int j = 0; j < 8; j++) acc[i][j] += a[i]*b[j];
        }
        __syncthreads();
    }

    #pragma unroll
    for (int i = 0; i < 8; i++) {
        const int orow = rowBase + ty*8 + i;
        const int b_ = orow >> 11;
        const int s_ = orow & (SEQ-1);
        #pragma unroll
        for (int j = 0; j < 8; j++) {
            const int oc = colBase + tx*8 + j;
            const float v = acc[i][j] + bias[oc];
            const int head = oc / 192;
            const int rem  = oc - head*192;
            const int t    = rem >> 6;
            const int dim  = rem & 63;
            const size_t dst = ((size_t)(b_*NHEADS + head)*SEQ + s_)*HDIM + dim;
            float* buf = (t == 0) ? g_q : (t == 1) ? g_k : g_v;
            buf[dst] = v;
        }
    }
}

// ---------------------------------------------------------------------------
// Flash attention with bf16 mma.sync (HMMA), bf16x3 for QK^T, bf16 for PV.
// CTA: 128 q-rows x (b,h). 8 warps, warp w owns q rows [16w,16w+16).
// K-tile = 64. smem: Q staging (bf16 hi/lo) reused as K hi/lo + V hi.
// ---------------------------------------------------------------------------
#define FP 72   // bf16 pitch (64 + 8 pad)

__device__ __forceinline__ unsigned sptr(const void* p) {
    return (unsigned)__cvta_generic_to_shared(p);
}
__device__ __forceinline__ unsigned packbf(float a, float b) {
    __nv_bfloat162 h = __halves2bfloat162(__float2bfloat16(a), __float2bfloat16(b));
    return *(unsigned*)&h;
}

#define LDSM4(R0,R1,R2,R3,ADDR) \
    asm volatile("ldmatrix.sync.aligned.m8n8.x4.shared.b16 {%0,%1,%2,%3},[%4];" \
        : "=r"(R0),"=r"(R1),"=r"(R2),"=r"(R3) : "r"(ADDR))
#define LDSM4T(R0,R1,R2,R3,ADDR) \
    asm volatile("ldmatrix.sync.aligned.m8n8.x4.trans.shared.b16 {%0,%1,%2,%3},[%4];" \
        : "=r"(R0),"=r"(R1),"=r"(R2),"=r"(R3) : "r"(ADDR))
#define MMA(D,A0,A1,A2,A3,B0,B1) \
    asm volatile("mma.sync.aligned.m16n8k16.row.col.f32.bf16.bf16.f32 " \
        "{%0,%1,%2,%3},{%4,%5,%6,%7},{%8,%9},{%0,%1,%2,%3};" \
        : "+f"(D[0]),"+f"(D[1]),"+f"(D[2]),"+f"(D[3]) \
        : "r"(A0),"r"(A1),"r"(A2),"r"(A3),"r"(B0),"r"(B1))

__global__ __launch_bounds__(256) void flash_mma_kernel()
{
    __shared__ __align__(16) char sm[2*128*FP*2];  // 36864 B
    __nv_bfloat16* sQh = (__nv_bfloat16*)sm;              // [128][FP]
    __nv_bfloat16* sQl = (__nv_bfloat16*)(sm + 128*FP*2); // [128][FP]
    __nv_bfloat16* sKh = (__nv_bfloat16*)sm;              // [64][FP]
    __nv_bfloat16* sKl = (__nv_bfloat16*)(sm + 64*FP*2);  // [64][FP]
    __nv_bfloat16* sVh = (__nv_bfloat16*)(sm + 128*FP*2); // [64][FP]

    const int tid  = threadIdx.x;
    const int lane = tid & 31;
    const int warp = tid >> 5;
    const int g    = lane >> 2;
    const int t    = lane & 3;
    const int h    = blockIdx.y;
    const int b    = blockIdx.z;
    const size_t base = (size_t)(b*NHEADS + h)*SEQ*HDIM;
    const float* Qg = g_q + base + (size_t)blockIdx.x*128*HDIM;
    const float* Kg = g_k + base;
    const float* Vg = g_v + base;

    // --- Stage Q (scaled by 1/8, split hi/lo) ---
    #pragma unroll
    for (int p = 0; p < 8; p++) {
        const int idx = tid + p*256;
        const int r = idx >> 4, c = (idx & 15) * 4;
        float4 v = *(const float4*)(Qg + r*HDIM + c);
        v.x *= 0.125f; v.y *= 0.125f; v.z *= 0.125f; v.w *= 0.125f;
        __nv_bfloat16 h0=__float2bfloat16(v.x), h1=__float2bfloat16(v.y),
                      h2=__float2bfloat16(v.z), h3=__float2bfloat16(v.w);
        __nv_bfloat16* hp = sQh + r*FP + c;
        ((__nv_bfloat162*)hp)[0] = __halves2bfloat162(h0,h1);
        ((__nv_bfloat162*)hp)[1] = __halves2bfloat162(h2,h3);
        __nv_bfloat16 l0=__float2bfloat16(v.x-__bfloat162float(h0)),
                      l1=__float2bfloat16(v.y-__bfloat162float(h1)),
                      l2=__float2bfloat16(v.z-__bfloat162float(h2)),
                      l3=__float2bfloat16(v.w-__bfloat162float(h3));
        __nv_bfloat16* lp = sQl + r*FP + c;
        ((__nv_bfloat162*)lp)[0] = __halves2bfloat162(l0,l1);
        ((__nv_bfloat162*)lp)[1] = __halves2bfloat162(l2,l3);
    }
    __syncthreads();

    // --- Q fragments to registers (4 k-steps over d) ---
    unsigned Qh[4][4], Ql[4][4];
    {
        const int row = warp*16 + (lane & 15);
        const int cb  = (lane >> 4) * 8;
        #pragma unroll
        for (int ks = 0; ks < 4; ks++) {
            LDSM4(Qh[ks][0],Qh[ks][1],Qh[ks][2],Qh[ks][3], sptr(sQh + row*FP + ks*16 + cb));
            LDSM4(Ql[ks][0],Ql[ks][1],Ql[ks][2],Ql[ks][3], sptr(sQl + row*FP + ks*16 + cb));
        }
    }
    __syncthreads();   // Q buffers now reusable for K/V

    float Oacc[8][4];
    #pragma unroll
    for (int j = 0; j < 8; j++)
        #pragma unroll
        for (int i = 0; i < 4; i++) Oacc[j][i] = 0.f;
    float m0 = -1e30f, m1 = -1e30f, l0s = 0.f, l1s = 0.f;

    for (int kt = 0; kt < SEQ/64; kt++) {
        const float* Kt = Kg + (size_t)kt*64*HDIM;
        const float* Vt = Vg + (size_t)kt*64*HDIM;
        // Stage K (hi/lo) and V (hi)
        #pragma unroll
        for (int p = 0; p < 4; p++) {
            const int idx = tid + p*256;
            const int r = idx >> 4, c = (idx & 15) * 4;
            float4 kv = *(const float4*)(Kt + r*HDIM + c);
            __nv_bfloat16 h0=__float2bfloat16(kv.x), h1=__float2bfloat16(kv.y),
                          h2=__float2bfloat16(kv.z), h3=__float2bfloat16(kv.w);
            __nv_bfloat16* hp = sKh + r*FP + c;
            ((__nv_bfloat162*)hp)[0] = __halves2bfloat162(h0,h1);
            ((__nv_bfloat162*)hp)[1] = __halves2bfloat162(h2,h3);
            __nv_bfloat16 q0=__float2bfloat16(kv.x-__bfloat162float(h0)),
                          q1=__float2bfloat16(kv.y-__bfloat162float(h1)),
                          q2=__float2bfloat16(kv.z-__bfloat162float(h2)),
                          q3=__float2bfloat16(kv.w-__bfloat162float(h3));
            __nv_bfloat16* lp = sKl + r*FP + c;
            ((__nv_bfloat162*)lp)[0] = __halves2bfloat162(q0,q1);
            ((__nv_bfloat162*)lp)[1] = __halves2bfloat162(q2,q3);
            float4 vv = *(const float4*)(Vt + r*HDIM + c);
            __nv_bfloat16* vp = sVh + r*FP + c;
            ((__nv_bfloat162*)vp)[0] = __halves2bfloat162(__float2bfloat16(vv.x),__float2bfloat16(vv.y));
            ((__nv_bfloat162*)vp)[1] = __halves2bfloat162(__float2bfloat16(vv.z),__float2bfloat16(vv.w));
        }
        __syncthreads();

        // S = (Q/8) K^T  via bf16x3
        float S[8][4];
        #pragma unroll
        for (int j = 0; j < 8; j++)
            #pragma unroll
            for (int i = 0; i < 4; i++) S[j][i] = 0.f;

        #pragma unroll
        for (int ks = 0; ks < 4; ks++) {
            #pragma unroll
            for (int nb = 0; nb < 4; nb++) {
                const int row = nb*16 + (lane & 15);
                const int col = ks*16 + (lane >> 4)*8;
                unsigned kh0,kh1,kh2,kh3, kl0,kl1,kl2,kl3;
                LDSM4(kh0,kh1,kh2,kh3, sptr(sKh + row*FP + col));
                LDSM4(kl0,kl1,kl2,kl3, sptr(sKl + row*FP + col));
                // n-block 2nb uses {r0,r2}, 2nb+1 uses {r1,r3}
                MMA(S[2*nb],   Qh[ks][0],Qh[ks][1],Qh[ks][2],Qh[ks][3], kh0,kh2);
                MMA(S[2*nb],   Qh[ks][0],Qh[ks][1],Qh[ks][2],Qh[ks][3], kl0,kl2);
                MMA(S[2*nb],   Ql[ks][0],Ql[ks][1],Ql[ks][2],Ql[ks][3], kh0,kh2);
                MMA(S[2*nb+1], Qh[ks][0],Qh[ks][1],Qh[ks][2],Qh[ks][3], kh1,kh3);
                MMA(S[2*nb+1], Qh[ks][0],Qh[ks][1],Qh[ks][2],Qh[ks][3], kl1,kl3);
                MMA(S[2*nb+1], Ql[ks][0],Ql[ks][1],Ql[ks][2],Ql[ks][3], kh1,kh3);
            }
        }

        // Online softmax on fragment layout (rows g and g+8)
        float mx0 = -1e30f, mx1 = -1e30f;
        #pragma unroll
        for (int j = 0; j < 8; j++) {
            mx0 = fmaxf(mx0, fmaxf(S[j][0], S[j][1]));
            mx1 = fmaxf(mx1, fmaxf(S[j][2], S[j][3]));
        }
        mx0 = fmaxf(mx0, __shfl_xor_sync(0xffffffffu, mx0, 1));
        mx0 = fmaxf(mx0, __shfl_xor_sync(0xffffffffu, mx0, 2));
        mx1 = fmaxf(mx1, __shfl_xor_sync(0xffffffffu, mx1, 1));
        mx1 = fmaxf(mx1, __shfl_xor_sync(0xffffffffu, mx1, 2));
        const float mn0 = fmaxf(m0, mx0);
        const float mn1 = fmaxf(m1, mx1);

        float sum0 = 0.f, sum1 = 0.f;
        #pragma unroll
        for (int j = 0; j < 8; j++) {
            S[j][0] = __expf(S[j][0] - mn0); sum0 += S[j][0];
            S[j][1] = __expf(S[j][1] - mn0); sum0 += S[j][1];
            S[j][2] = __expf(S[j][2] - mn1); sum1 += S[j][2];
            S[j][3] = __expf(S[j][3] - mn1); sum1 += S[j][3];
        }
        sum0 += __shfl_xor_sync(0xffffffffu, sum0, 1);
        sum0 += __shfl_xor_sync(0xffffffffu, sum0, 2);
        sum1 += __shfl_xor_sync(0xffffffffu, sum1, 1);
        sum1 += __shfl_xor_sync(0xffffffffu, sum1, 2);

        const float sc0 = __expf(m0 - mn0);
        const float sc1 = __expf(m1 - mn1);
        l0s = l0s*sc0 + sum0;
        l1s = l1s*sc1 + sum1;
        m0 = mn0; m1 = mn1;
        #pragma unroll
        for (int j = 0; j < 8; j++) {
            Oacc[j][0] *= sc0; Oacc[j][1] *= sc0;
            Oacc[j][2] *= sc1; Oacc[j][3] *= sc1;
        }

        // P fragments (reuse S accumulator layout as A fragments)
        unsigned P[4][4];
        #pragma unroll
        for (int ks = 0; ks < 4; ks++) {
            P[ks][0] = packbf(S[2*ks  ][0], S[2*ks  ][1]);
            P[ks][1] = packbf(S[2*ks  ][2], S[2*ks  ][3]);
            P[ks][2] = packbf(S[2*ks+1][0], S[2*ks+1][1]);
            P[ks][3] = packbf(S[2*ks+1][2], S[2*ks+1][3]);
        }

        // O += P V   (V via ldmatrix.trans: {r0,r1} = d-block 2nb, {r2,r3} = 2nb+1)
        #pragma unroll
        for (int ks = 0; ks < 4; ks++) {
            #pragma unroll
            for (int nb = 0; nb < 4; nb++) {
                const int row = ks*16 + (lane & 15);
                const int col = nb*16 + (lane >> 4)*8;
                unsigned v0,v1,v2,v3;
                LDSM4T(v0,v1,v2,v3, sptr(sVh + row*FP + col));
                MMA(Oacc[2*nb],   P[ks][0],P[ks][1],P[ks][2],P[ks][3], v0,v1);
                MMA(Oacc[2*nb+1], P[ks][0],P[ks][1],P[ks][2],P[ks][3], v2,v3);
            }
        }
        __syncthreads();
    }

    // Epilogue: normalize + write [B,S,E]
    const float inv0 = 1.f / l0s;
    const float inv1 = 1.f / l1s;
    const int q = blockIdx.x*128 + warp*16;
    float* dst = g_attn + ((size_t)b*SEQ + q)*EMBED + h*HDIM;
    #pragma unroll
    for (int j = 0; j < 8; j++) {
        const int col = j*8 + t*2;
        *(float2*)(dst + (size_t)g*EMBED + col) =
            make_float2(Oacc[j][0]*inv0, Oacc[j][1]*inv0);
        *(float2*)(dst + (size_t)(g+8)*EMBED + col) =
            make_float2(Oacc[j][2]*inv1, Oacc[j][3]*inv1);
    }
}

// ---------------------------------------------------------------------------
// Output projection (fp32 SGEMM, unchanged this round)
// ---------------------------------------------------------------------------
__global__ __launch_bounds__(256) void out_gemm_kernel(
    const float* __restrict__ W, const float* __restrict__ bias,
    float* __restrict__ out)
{
    __shared__ float As[16][128];
    __shared__ float Bs[16][128];
    const int tid = threadIdx.x;
    const int tx  = tid & 15;
    const int ty  = tid >> 4;
    const int rowBase = blockIdx.y * 128;
    const int colBase = blockIdx.x * 128;
    const int lr = tid >> 2;
    const int lc = tid & 3;

    float acc[8][8];
    #pragma unroll
    for (int i = 0; i < 8; i++)
        #pragma unroll
        for (int j = 0; j < 8; j++) acc[i][j] = 0.f;

    for (int k0 = 0; k0 < EMBED; k0 += 16) {
        #pragma unroll
        for (int p = 0; p < 2; p++) {
            const int r = lr + p*64;
            float4 va = *(const float4*)(g_attn + (size_t)(rowBase + r)*EMBED + k0 + lc*4);
            As[lc*4+0][r] = va.x; As[lc*4+1][r] = va.y;
            As[lc*4+2][r] = va.z; As[lc*4+3][r] = va.w;
            float4 vb = *(const float4*)(W + (size_t)(colBase + r)*EMBED + k0 + lc*4);
            Bs[lc*4+0][r] = vb.x; Bs[lc*4+1][r] = vb.y;
            Bs[lc*4+2][r] = vb.z; Bs[lc*4+3][r] = vb.w;
        }
        __syncthreads();
        #pragma unroll
        for (int k = 0; k < 16; k++) {
            float a[8], b[8];
            *(float4*)&a[0] = *(const float4*)&As[k][ty*8];
            *(float4*)&a[4] = *(const float4*)&As[k][ty*8+4];
            *(float4*)&b[0] = *(const float4*)&Bs[k][tx*8];
            *(float4*)&b[4] = *(const float4*)&Bs[k][tx*8+4];
            #pragma unroll
            for (int i = 0; i < 8; i++)
                #pragma unroll
                for (int j = 0; j < 8; j++) acc[i][j] += a[i]*b[j];
        }
        __syncthreads();
    }

    #pragma unroll
    for (int i = 0; i < 8; i++) {
        const int orow = rowBase + ty*8 + i;
        const int oc0  = colBase + tx*8;
        float4 r0 = make_float4(acc[i][0] + bias[oc0+0], acc[i][1] + bias[oc0+1],
                                acc[i][2] + bias[oc0+2], acc[i][3] + bias[oc0+3]);
        float4 r1 = make_float4(acc[i][4] + bias[oc0+4], acc[i][5] + bias[oc0+5],
                                acc[i][6] + bias[oc0+6], acc[i][7] + bias[oc0+7]);
        *(float4*)(out + (size_t)orow*EMBED + oc0    ) = r0;
        *(float4*)(out + (size_t)orow*EMBED + oc0 + 4) = r1;
    }
}

extern "C" void kernel_launch(void* const* d_in, const int* in_sizes, int n_in,
                              void* d_out, int out_size)
{
    const float* x     = (const float*)d_in[0];
    const float* qkv_w = (const float*)d_in[1];
    const float* qkv_b = (const float*)d_in[2];
    const float* out_w = (const float*)d_in[3];
    const float* out_b = (const float*)d_in[4];
    float* out = (float*)d_out;

    qkv_gemm_kernel<<<dim3(QKVN/128, MTOT/128), 256>>>(x, qkv_w, qkv_b);
    flash_mma_kernel<<<dim3(SEQ/128, NHEADS, BATCH), 256>>>();
    out_gemm_kernel<<<dim3(EMBED/128, MTOT/128), 256>>>(out_w, out_b, out);
}

// round 7
// speedup vs baseline: 4.4426x; 1.6334x over previous
#include <cuda_runtime.h>
#include <cuda_bf16.h>
#include <cstdint>

#define NHEADS 16
#define HDIM   64
#define EMBED  1024
#define BATCH  2
#define SEQ    2048
#define MTOT   (BATCH*SEQ)          // 4096
#define QKVN   (3*EMBED)            // 3072

// Scratch (static device globals — referenced from DEVICE code only!)
__device__ float g_q[BATCH*NHEADS*SEQ*HDIM];     // [B,H,S,d]
__device__ float g_k[BATCH*NHEADS*SEQ*HDIM];
__device__ float g_v[BATCH*NHEADS*SEQ*HDIM];
__device__ float g_attn[BATCH*SEQ*EMBED];        // [B,S,E]

// ===========================================================================
// Common helpers
// ===========================================================================
__device__ __forceinline__ unsigned sptr(const void* p) {
    return (unsigned)__cvta_generic_to_shared(p);
}
__device__ __forceinline__ unsigned packbf(float a, float b) {
    __nv_bfloat162 h = __halves2bfloat162(__float2bfloat16(a), __float2bfloat16(b));
    return *(unsigned*)&h;
}
// pack 2 floats to bf16x2 {lo=a, hi=b}
__device__ __forceinline__ uint32_t cvt2(float a, float b) {
    uint32_t r;
    asm("cvt.rn.bf16x2.f32 %0, %1, %2;" : "=r"(r) : "f"(b), "f"(a));
    return r;
}
// split float4 into bf16 hi (uint2) and residual lo (uint2)
__device__ __forceinline__ void split4(float4 v, uint2& hi, uint2& lo) {
    uint32_t h01 = cvt2(v.x, v.y);
    uint32_t h23 = cvt2(v.z, v.w);
    float rx = v.x - __uint_as_float(h01 << 16);
    float ry = v.y - __uint_as_float(h01 & 0xffff0000u);
    float rz = v.z - __uint_as_float(h23 << 16);
    float rw = v.w - __uint_as_float(h23 & 0xffff0000u);
    lo = make_uint2(cvt2(rx, ry), cvt2(rz, rw));
    hi = make_uint2(h01, h23);
}

#define LDSM4(R0,R1,R2,R3,ADDR) \
    asm volatile("ldmatrix.sync.aligned.m8n8.x4.shared.b16 {%0,%1,%2,%3},[%4];" \
        : "=r"(R0),"=r"(R1),"=r"(R2),"=r"(R3) : "r"(ADDR))
#define LDSM4T(R0,R1,R2,R3,ADDR) \
    asm volatile("ldmatrix.sync.aligned.m8n8.x4.trans.shared.b16 {%0,%1,%2,%3},[%4];" \
        : "=r"(R0),"=r"(R1),"=r"(R2),"=r"(R3) : "r"(ADDR))
#define MMA(D,A0,A1,A2,A3,B0,B1) \
    asm volatile("mma.sync.aligned.m16n8k16.row.col.f32.bf16.bf16.f32 " \
        "{%0,%1,%2,%3},{%4,%5,%6,%7},{%8,%9},{%0,%1,%2,%3};" \
        : "+f"(D[0]),"+f"(D[1]),"+f"(D[2]),"+f"(D[3]) \
        : "r"(A0),"r"(A1),"r"(A2),"r"(A3),"r"(B0),"r"(B1))

// ===========================================================================
// bf16x3 HMMA GEMM: C[M, N] = A[M,1024] @ B[N,1024]^T (+bias)
// CTA tile 128x128, 8 warps (warp tile 32x64), K-tile 32, static smem 40 KB.
// EPI=0: A = Ag param (x), scatter into g_q/g_k/g_v.
// EPI=1: A = g_attn (device symbol, read in device code!), write to Cg.
// ===========================================================================
#define KT  32
#define GFP 40      // smem pitch in bf16 elements (32 + 8 pad; 80 B)

template<int EPI>
__global__ __launch_bounds__(256) void hmma_gemm_kernel(
    const float* __restrict__ Ag, const float* __restrict__ Bg,
    const float* __restrict__ bias, float* __restrict__ Cg)
{
    __shared__ __align__(16) __nv_bfloat16 sAh[128*GFP];
    __shared__ __align__(16) __nv_bfloat16 sAl[128*GFP];
    __shared__ __align__(16) __nv_bfloat16 sBh[128*GFP];
    __shared__ __align__(16) __nv_bfloat16 sBl[128*GFP];

    // CRITICAL: device symbols must be referenced from device code, not passed
    // from host (host-side symbol address is the host shadow, reads zeros).
    const float* __restrict__ Aptr = (EPI == 0) ? Ag : (const float*)g_attn;

    const int tid  = threadIdx.x;
    const int lane = tid & 31;
    const int warp = tid >> 5;
    const int mw   = warp & 3;      // 4 m-blocks of 32 rows
    const int nw   = warp >> 2;     // 2 n-blocks of 64 cols
    const int g    = lane >> 2;
    const int t    = lane & 3;
    const int rowBase = blockIdx.y * 128;
    const int colBase = blockIdx.x * 128;

    float acc[2][8][4];
    #pragma unroll
    for (int i = 0; i < 2; i++)
        #pragma unroll
        for (int j = 0; j < 8; j++)
            #pragma unroll
            for (int c = 0; c < 4; c++) acc[i][j][c] = 0.f;

    for (int kt = 0; kt < EMBED/KT; kt++) {
        const int k0 = kt * KT;
        __syncthreads();
        // Stage A[128][32] and B[128][32], split hi/lo
        #pragma unroll
        for (int p = 0; p < 4; p++) {
            const int idx = tid + p*256;
            const int r = idx >> 3;          // 0..127
            const int c = (idx & 7) * 4;     // 0..28
            float4 va = *(const float4*)(Aptr + (size_t)(rowBase + r)*EMBED + k0 + c);
            uint2 hi, lo; split4(va, hi, lo);
            *(uint2*)(sAh + r*GFP + c) = hi;
            *(uint2*)(sAl + r*GFP + c) = lo;
            float4 vb = *(const float4*)(Bg + (size_t)(colBase + r)*EMBED + k0 + c);
            split4(vb, hi, lo);
            *(uint2*)(sBh + r*GFP + c) = hi;
            *(uint2*)(sBl + r*GFP + c) = lo;
        }
        __syncthreads();

        // Compute: 2 k16 steps
        #pragma unroll
        for (int ks = 0; ks < 2; ks++) {
            const int col = ks*16 + (lane >> 4)*8;   // element offset
            unsigned Ah[2][4], Al[2][4];
            #pragma unroll
            for (int i = 0; i < 2; i++) {
                const int row = mw*32 + i*16 + (lane & 15);
                LDSM4(Ah[i][0],Ah[i][1],Ah[i][2],Ah[i][3], sptr(sAh + row*GFP + col));
                LDSM4(Al[i][0],Al[i][1],Al[i][2],Al[i][3], sptr(sAl + row*GFP + col));
            }
            #pragma unroll
            for (int bt = 0; bt < 4; bt++) {
                const int row = nw*64 + bt*16 + (lane & 15);
                unsigned bh0,bh1,bh2,bh3, bl0,bl1,bl2,bl3;
                LDSM4(bh0,bh1,bh2,bh3, sptr(sBh + row*GFP + col));
                LDSM4(bl0,bl1,bl2,bl3, sptr(sBl + row*GFP + col));
                #pragma unroll
                for (int i = 0; i < 2; i++) {
                    MMA(acc[i][2*bt],   Ah[i][0],Ah[i][1],Ah[i][2],Ah[i][3], bh0,bh2);
                    MMA(acc[i][2*bt],   Ah[i][0],Ah[i][1],Ah[i][2],Ah[i][3], bl0,bl2);
                    MMA(acc[i][2*bt],   Al[i][0],Al[i][1],Al[i][2],Al[i][3], bh0,bh2);
                    MMA(acc[i][2*bt+1], Ah[i][0],Ah[i][1],Ah[i][2],Ah[i][3], bh1,bh3);
                    MMA(acc[i][2*bt+1], Ah[i][0],Ah[i][1],Ah[i][2],Ah[i][3], bl1,bl3);
                    MMA(acc[i][2*bt+1], Al[i][0],Al[i][1],Al[i][2],Al[i][3], bh1,bh3);
                }
            }
        }
    }

    // Epilogue
    const int cb = colBase + nw*64;      // 64-aligned -> single (head,typ) block
    if (EPI == 0) {
        const int head = cb / 192;
        const int rem  = cb - head*192;
        const int typ  = rem >> 6;
        float* buf = (typ == 0) ? g_q : (typ == 1) ? g_k : g_v;
        #pragma unroll
        for (int i = 0; i < 2; i++) {
            #pragma unroll
            for (int half = 0; half < 2; half++) {
                const int row = rowBase + mw*32 + i*16 + g + half*8;
                const int b_ = row >> 11, s_ = row & (SEQ - 1);
                float* dst = buf + ((((size_t)(b_*NHEADS + head))*SEQ + s_) << 6);
                #pragma unroll
                for (int j = 0; j < 8; j++) {
                    const int d = j*8 + t*2;
                    float2 bs = *(const float2*)(bias + cb + d);
                    *(float2*)(dst + d) = make_float2(acc[i][j][2*half]   + bs.x,
                                                      acc[i][j][2*half+1] + bs.y);
                }
            }
        }
    } else {
        #pragma unroll
        for (int i = 0; i < 2; i++) {
            #pragma unroll
            for (int half = 0; half < 2; half++) {
                const int row = rowBase + mw*32 + i*16 + g + half*8;
                float* dst = Cg + (size_t)row*EMBED + cb;
                #pragma unroll
                for (int j = 0; j < 8; j++) {
                    const int d = j*8 + t*2;
                    float2 bs = *(const float2*)(bias + cb + d);
                    *(float2*)(dst + d) = make_float2(acc[i][j][2*half]   + bs.x,
                                                      acc[i][j][2*half+1] + bs.y);
                }
            }
        }
    }
}

// ===========================================================================
// Flash attention: bf16x3 QK^T, Px2 PV (Ph·V + Pl·V, V single bf16).
// 128 q-rows per CTA, 8 warps. Based on validated R2 kernel.
// ===========================================================================
#define FP 72   // bf16 pitch (64 + 8 pad)

__global__ __launch_bounds__(256) void flash_mma_kernel()
{
    __shared__ __align__(16) char sm[2*128*FP*2];  // 36864 B
    __nv_bfloat16* sQh = (__nv_bfloat16*)sm;              // [128][FP]
    __nv_bfloat16* sQl = (__nv_bfloat16*)(sm + 128*FP*2); // [128][FP]
    __nv_bfloat16* sKh = (__nv_bfloat16*)sm;              // [64][FP]
    __nv_bfloat16* sKl = (__nv_bfloat16*)(sm + 64*FP*2);  // [64][FP]
    __nv_bfloat16* sVh = (__nv_bfloat16*)(sm + 128*FP*2); // [64][FP]

    const int tid  = threadIdx.x;
    const int lane = tid & 31;
    const int warp = tid >> 5;
    const int g    = lane >> 2;
    const int t    = lane & 3;
    const int h    = blockIdx.y;
    const int b    = blockIdx.z;
    const size_t base = (size_t)(b*NHEADS + h)*SEQ*HDIM;
    const float* Qg = g_q + base + (size_t)blockIdx.x*128*HDIM;
    const float* Kg = g_k + base;
    const float* Vg = g_v + base;

    // --- Stage Q (scaled by 1/8, split hi/lo) ---
    #pragma unroll
    for (int p = 0; p < 8; p++) {
        const int idx = tid + p*256;
        const int r = idx >> 4, c = (idx & 15) * 4;
        float4 v = *(const float4*)(Qg + r*HDIM + c);
        v.x *= 0.125f; v.y *= 0.125f; v.z *= 0.125f; v.w *= 0.125f;
        uint2 hi, lo; split4(v, hi, lo);
        *(uint2*)(sQh + r*FP + c) = hi;
        *(uint2*)(sQl + r*FP + c) = lo;
    }
    __syncthreads();

    // --- Q fragments to registers (4 k-steps over d) ---
    unsigned Qh[4][4], Ql[4][4];
    {
        const int row = warp*16 + (lane & 15);
        const int cb  = (lane >> 4) * 8;
        #pragma unroll
        for (int ks = 0; ks < 4; ks++) {
            LDSM4(Qh[ks][0],Qh[ks][1],Qh[ks][2],Qh[ks][3], sptr(sQh + row*FP + ks*16 + cb));
            LDSM4(Ql[ks][0],Ql[ks][1],Ql[ks][2],Ql[ks][3], sptr(sQl + row*FP + ks*16 + cb));
        }
    }
    __syncthreads();   // Q buffers now reusable for K/V

    float Oacc[8][4];
    #pragma unroll
    for (int j = 0; j < 8; j++)
        #pragma unroll
        for (int i = 0; i < 4; i++) Oacc[j][i] = 0.f;
    float m0 = -1e30f, m1 = -1e30f, l0s = 0.f, l1s = 0.f;

    for (int kt = 0; kt < SEQ/64; kt++) {
        const float* Kt = Kg + (size_t)kt*64*HDIM;
        const float* Vt = Vg + (size_t)kt*64*HDIM;
        // Stage K (hi/lo) and V (hi)
        #pragma unroll
        for (int p = 0; p < 4; p++) {
            const int idx = tid + p*256;
            const int r = idx >> 4, c = (idx & 15) * 4;
            float4 kv = *(const float4*)(Kt + r*HDIM + c);
            uint2 khi, klo; split4(kv, khi, klo);
            *(uint2*)(sKh + r*FP + c) = khi;
            *(uint2*)(sKl + r*FP + c) = klo;
            float4 vv = *(const float4*)(Vt + r*HDIM + c);
            __nv_bfloat16* vp = sVh + r*FP + c;
            ((uint32_t*)vp)[0] = cvt2(vv.x, vv.y);
            ((uint32_t*)vp)[1] = cvt2(vv.z, vv.w);
        }
        __syncthreads();

        // S = (Q/8) K^T  via bf16x3
        float S[8][4];
        #pragma unroll
        for (int j = 0; j < 8; j++)
            #pragma unroll
            for (int i = 0; i < 4; i++) S[j][i] = 0.f;

        #pragma unroll
        for (int ks = 0; ks < 4; ks++) {
            #pragma unroll
            for (int nb = 0; nb < 4; nb++) {
                const int row = nb*16 + (lane & 15);
                const int col = ks*16 + (lane >> 4)*8;
                unsigned kh0,kh1,kh2,kh3, kl0,kl1,kl2,kl3;
                LDSM4(kh0,kh1,kh2,kh3, sptr(sKh + row*FP + col));
                LDSM4(kl0,kl1,kl2,kl3, sptr(sKl + row*FP + col));
                MMA(S[2*nb],   Qh[ks][0],Qh[ks][1],Qh[ks][2],Qh[ks][3], kh0,kh2);
                MMA(S[2*nb],   Qh[ks][0],Qh[ks][1],Qh[ks][2],Qh[ks][3], kl0,kl2);
                MMA(S[2*nb],   Ql[ks][0],Ql[ks][1],Ql[ks][2],Ql[ks][3], kh0,kh2);
                MMA(S[2*nb+1], Qh[ks][0],Qh[ks][1],Qh[ks][2],Qh[ks][3], kh1,kh3);
                MMA(S[2*nb+1], Qh[ks][0],Qh[ks][1],Qh[ks][2],Qh[ks][3], kl1,kl3);
                MMA(S[2*nb+1], Ql[ks][0],Ql[ks][1],Ql[ks][2],Ql[ks][3], kh1,kh3);
            }
        }

        // Online softmax on fragment layout (rows g and g+8)
        float mx0 = -1e30f, mx1 = -1e30f;
        #pragma unroll
        for (int j = 0; j < 8; j++) {
            mx0 = fmaxf(mx0, fmaxf(S[j][0], S[j][1]));
            mx1 = fmaxf(mx1, fmaxf(S[j][2], S[j][3]));
        }
        mx0 = fmaxf(mx0, __shfl_xor_sync(0xffffffffu, mx0, 1));
        mx0 = fmaxf(mx0, __shfl_xor_sync(0xffffffffu, mx0, 2));
        mx1 = fmaxf(mx1, __shfl_xor_sync(0xffffffffu, mx1, 1));
        mx1 = fmaxf(mx1, __shfl_xor_sync(0xffffffffu, mx1, 2));
        const float mn0 = fmaxf(m0, mx0);
        const float mn1 = fmaxf(m1, mx1);

        float sum0 = 0.f, sum1 = 0.f;
        #pragma unroll
        for (int j = 0; j < 8; j++) {
            S[j][0] = __expf(S[j][0] - mn0); sum0 += S[j][0];
            S[j][1] = __expf(S[j][1] - mn0); sum0 += S[j][1];
            S[j][2] = __expf(S[j][2] - mn1); sum1 += S[j][2];
            S[j][3] = __expf(S[j][3] - mn1); sum1 += S[j][3];
        }
        sum0 += __shfl_xor_sync(0xffffffffu, sum0, 1);
        sum0 += __shfl_xor_sync(0xffffffffu, sum0, 2);
        sum1 += __shfl_xor_sync(0xffffffffu, sum1, 1);
        sum1 += __shfl_xor_sync(0xffffffffu, sum1, 2);

        const float sc0 = __expf(m0 - mn0);
        const float sc1 = __expf(m1 - mn1);
        l0s = l0s*sc0 + sum0;
        l1s = l1s*sc1 + sum1;
        m0 = mn0; m1 = mn1;
        #pragma unroll
        for (int j = 0; j < 8; j++) {
            Oacc[j][0] *= sc0; Oacc[j][1] *= sc0;
            Oacc[j][2] *= sc1; Oacc[j][3] *= sc1;
        }

        // P fragments: hi + residual lo (Px2)
        unsigned Ph[4][4], Pl[4][4];
        #pragma unroll
        for (int ks = 0; ks < 4; ks++) {
            #pragma unroll
            for (int q = 0; q < 2; q++) {
                const int j = 2*ks + q;
                uint32_t h01 = cvt2(S[j][0], S[j][1]);
                uint32_t h23 = cvt2(S[j][2], S[j][3]);
                float r0 = S[j][0] - __uint_as_float(h01 << 16);
                float r1 = S[j][1] - __uint_as_float(h01 & 0xffff0000u);
                float r2 = S[j][2] - __uint_as_float(h23 << 16);
                float r3 = S[j][3] - __uint_as_float(h23 & 0xffff0000u);
                Ph[ks][2*q]   = h01; Ph[ks][2*q+1] = h23;
                Pl[ks][2*q]   = cvt2(r0, r1); Pl[ks][2*q+1] = cvt2(r2, r3);
            }
        }

        // O += (Ph + Pl) V   (V via ldmatrix.trans)
        #pragma unroll
        for (int ks = 0; ks < 4; ks++) {
            #pragma unroll
            for (int nb = 0; nb < 4; nb++) {
                const int row = ks*16 + (lane & 15);
                const int col = nb*16 + (lane >> 4)*8;
                unsigned v0,v1,v2,v3;
                LDSM4T(v0,v1,v2,v3, sptr(sVh + row*FP + col));
                MMA(Oacc[2*nb],   Ph[ks][0],Ph[ks][1],Ph[ks][2],Ph[ks][3], v0,v1);
                MMA(Oacc[2*nb],   Pl[ks][0],Pl[ks][1],Pl[ks][2],Pl[ks][3], v0,v1);
                MMA(Oacc[2*nb+1], Ph[ks][0],Ph[ks][1],Ph[ks][2],Ph[ks][3], v2,v3);
                MMA(Oacc[2*nb+1], Pl[ks][0],Pl[ks][1],Pl[ks][2],Pl[ks][3], v2,v3);
            }
        }
        __syncthreads();
    }

    // Epilogue: normalize + write [B,S,E]
    const float inv0 = 1.f / l0s;
    const float inv1 = 1.f / l1s;
    const int q = blockIdx.x*128 + warp*16;
    float* dst = g_attn + ((size_t)b*SEQ + q)*EMBED + h*HDIM;
    #pragma unroll
    for (int j = 0; j < 8; j++) {
        const int col = j*8 + t*2;
        *(float2*)(dst + (size_t)g*EMBED + col) =
            make_float2(Oacc[j][0]*inv0, Oacc[j][1]*inv0);
        *(float2*)(dst + (size_t)(g+8)*EMBED + col) =
            make_float2(Oacc[j][2]*inv1, Oacc[j][3]*inv1);
    }
}

// ===========================================================================
extern "C" void kernel_launch(void* const* d_in, const int* in_sizes, int n_in,
                              void* d_out, int out_size)
{
    const float* x     = (const float*)d_in[0];
    const float* qkv_w = (const float*)d_in[1];
    const float* qkv_b = (const float*)d_in[2];
    const float* out_w = (const float*)d_in[3];
    const float* out_b = (const float*)d_in[4];
    float* out = (float*)d_out;

    // QKV projection: [4096,3072]  (A = x from harness; scatter to device globals)
    hmma_gemm_kernel<0><<<dim3(QKVN/128, MTOT/128), 256>>>(x, qkv_w, qkv_b, nullptr);
    // Attention (device globals only)
    flash_mma_kernel<<<dim3(SEQ/128, NHEADS, BATCH), 256>>>();
    // Output projection: [4096,1024]  (A = g_attn read inside device code)
    hmma_gemm_kernel<1><<<dim3(EMBED/128, MTOT/128), 256>>>(nullptr, out_w, out_b, out);
}

// round 8
// speedup vs baseline: 4.7778x; 1.0755x over previous
#include <cuda_runtime.h>
#include <cuda_bf16.h>
#include <cstdint>

#define NHEADS 16
#define HDIM   64
#define EMBED  1024
#define BATCH  2
#define SEQ    2048
#define MTOT   (BATCH*SEQ)          // 4096
#define QKVN   (3*EMBED)            // 3072
#define QKV_ELEMS (BATCH*NHEADS*SEQ*HDIM)   // 4194304

// -------- device-global scratch (device-code references only!) -------------
__device__ __nv_bfloat16 g_xh[MTOT*EMBED],  g_xl[MTOT*EMBED];      // x hi/lo
__device__ __nv_bfloat16 g_wqh[QKVN*EMBED], g_wql[QKVN*EMBED];     // qkv_w hi/lo
__device__ __nv_bfloat16 g_woh[EMBED*EMBED], g_wol[EMBED*EMBED];   // out_w hi/lo
__device__ __nv_bfloat16 g_qh[QKV_ELEMS], g_ql[QKV_ELEMS];         // Q/8 hi/lo [B,H,S,d]
__device__ __nv_bfloat16 g_kh[QKV_ELEMS], g_kl[QKV_ELEMS];         // K hi/lo
__device__ __nv_bfloat16 g_vh[QKV_ELEMS];                          // V bf16
__device__ __nv_bfloat16 g_ah[MTOT*EMBED], g_al[MTOT*EMBED];       // attn hi/lo [B,S,E]

// ===========================================================================
// Helpers
// ===========================================================================
__device__ __forceinline__ unsigned sptr(const void* p) {
    return (unsigned)__cvta_generic_to_shared(p);
}
// pack 2 floats to bf16x2 {elem0=a, elem1=b}
__device__ __forceinline__ uint32_t cvt2(float a, float b) {
    uint32_t r;
    asm("cvt.rn.bf16x2.f32 %0, %1, %2;" : "=r"(r) : "f"(b), "f"(a));
    return r;
}
__device__ __forceinline__ void split2(float a, float b, uint32_t& hi, uint32_t& lo) {
    hi = cvt2(a, b);
    float ra = a - __uint_as_float(hi << 16);
    float rb = b - __uint_as_float(hi & 0xffff0000u);
    lo = cvt2(ra, rb);
}
__device__ __forceinline__ void split4(float4 v, uint2& hi, uint2& lo) {
    uint32_t h01 = cvt2(v.x, v.y);
    uint32_t h23 = cvt2(v.z, v.w);
    float rx = v.x - __uint_as_float(h01 << 16);
    float ry = v.y - __uint_as_float(h01 & 0xffff0000u);
    float rz = v.z - __uint_as_float(h23 << 16);
    float rw = v.w - __uint_as_float(h23 & 0xffff0000u);
    lo = make_uint2(cvt2(rx, ry), cvt2(rz, rw));
    hi = make_uint2(h01, h23);
}

#define CP16(SADDR, GPTR) \
    asm volatile("cp.async.cg.shared.global [%0], [%1], 16;" \
        :: "r"((uint32_t)(SADDR)), "l"(GPTR) : "memory")
#define CP_COMMIT() asm volatile("cp.async.commit_group;" ::: "memory")
#define CP_WAIT(N)  asm volatile("cp.async.wait_group %0;" :: "n"(N) : "memory")

#define LDSM4(R0,R1,R2,R3,ADDR) \
    asm volatile("ldmatrix.sync.aligned.m8n8.x4.shared.b16 {%0,%1,%2,%3},[%4];" \
        : "=r"(R0),"=r"(R1),"=r"(R2),"=r"(R3) : "r"(ADDR))
#define LDSM4T(R0,R1,R2,R3,ADDR) \
    asm volatile("ldmatrix.sync.aligned.m8n8.x4.trans.shared.b16 {%0,%1,%2,%3},[%4];" \
        : "=r"(R0),"=r"(R1),"=r"(R2),"=r"(R3) : "r"(ADDR))
#define MMA(D,A0,A1,A2,A3,B0,B1) \
    asm volatile("mma.sync.aligned.m16n8k16.row.col.f32.bf16.bf16.f32 " \
        "{%0,%1,%2,%3},{%4,%5,%6,%7},{%8,%9},{%0,%1,%2,%3};" \
        : "+f"(D[0]),"+f"(D[1]),"+f"(D[2]),"+f"(D[3]) \
        : "r"(A0),"r"(A1),"r"(A2),"r"(A3),"r"(B0),"r"(B1))

// ===========================================================================
// Pre-convert: qkv_w, out_w, x -> bf16 hi/lo global buffers
// ===========================================================================
#define N_QW4 (QKVN*EMBED/4)   // 786432
#define N_OW4 (EMBED*EMBED/4)  // 262144
#define N_X4  (MTOT*EMBED/4)   // 1048576

__global__ __launch_bounds__(256) void conv_kernel(
    const float* __restrict__ qkv_w, const float* __restrict__ out_w,
    const float* __restrict__ x)
{
    const int i = blockIdx.x*256 + threadIdx.x;
    uint2 hi, lo;
    if (i < N_QW4) {
        split4(((const float4*)qkv_w)[i], hi, lo);
        ((uint2*)g_wqh)[i] = hi; ((uint2*)g_wql)[i] = lo;
    }
    if (i < N_OW4) {
        split4(((const float4*)out_w)[i], hi, lo);
        ((uint2*)g_woh)[i] = hi; ((uint2*)g_wol)[i] = lo;
    }
    if (i < N_X4) {
        split4(((const float4*)x)[i], hi, lo);
        ((uint2*)g_xh)[i] = hi; ((uint2*)g_xl)[i] = lo;
    }
}

// ===========================================================================
// bf16x3 HMMA GEMM, cp.async double-buffered. CTA 128x128, warp 32x64, K=32.
// Buffer layout (bytes, per 40960B buffer): Ah@0 Al@10240 Bh@20480 Bl@30720,
// row pitch 80B (40 bf16).
// EPI=0: A=g_xh/l, B=g_wqh/l, scatter Q(h,l,*1/8)/K(h,l)/V(h) bf16.
// EPI=1: A=g_ah/l, B=g_woh/l, write fp32 out.
// ===========================================================================
#define GEMM_BUF  40960
#define GEMM_SMEM (2*GEMM_BUF)
#define NT_G      (EMBED/32)

__device__ __forceinline__ void gemm_stage(uint32_t sb,
    const __nv_bfloat16* __restrict__ Ah, const __nv_bfloat16* __restrict__ Al,
    const __nv_bfloat16* __restrict__ Bh, const __nv_bfloat16* __restrict__ Bl,
    int rowBase, int colBase, int k0, int tid)
{
    #pragma unroll
    for (int p = 0; p < 2; p++) {
        const int idx = tid + p*256;            // 0..511
        const int r = idx >> 2;                 // 0..127
        const int c = (idx & 3) * 8;            // elements 0,8,16,24
        const size_t ga = (size_t)(rowBase + r)*EMBED + k0 + c;
        const size_t gb = (size_t)(colBase + r)*EMBED + k0 + c;
        const uint32_t so = (uint32_t)(r*80 + c*2);
        CP16(sb + so,         Ah + ga);
        CP16(sb + 10240 + so, Al + ga);
        CP16(sb + 20480 + so, Bh + gb);
        CP16(sb + 30720 + so, Bl + gb);
    }
}

template<int EPI>
__global__ __launch_bounds__(256) void hmma_gemm_kernel(
    const float* __restrict__ bias, float* __restrict__ Cg)
{
    extern __shared__ __align__(16) char smc[];
    const uint32_t smb = sptr(smc);

    const __nv_bfloat16* Ah = (EPI == 0) ? g_xh  : g_ah;
    const __nv_bfloat16* Al = (EPI == 0) ? g_xl  : g_al;
    const __nv_bfloat16* Bh = (EPI == 0) ? g_wqh : g_woh;
    const __nv_bfloat16* Bl = (EPI == 0) ? g_wql : g_wol;

    const int tid  = threadIdx.x;
    const int lane = tid & 31;
    const int warp = tid >> 5;
    const int mw   = warp & 3;
    const int nw   = warp >> 2;
    const int g    = lane >> 2;
    const int t    = lane & 3;
    const int rowBase = blockIdx.y * 128;
    const int colBase = blockIdx.x * 128;

    float acc[2][8][4];
    #pragma unroll
    for (int i = 0; i < 2; i++)
        #pragma unroll
        for (int j = 0; j < 8; j++)
            #pragma unroll
            for (int c = 0; c < 4; c++) acc[i][j][c] = 0.f;

    gemm_stage(smb, Ah, Al, Bh, Bl, rowBase, colBase, 0, tid);
    CP_COMMIT();

    for (int kt = 0; kt < NT_G; kt++) {
        if (kt + 1 < NT_G) {
            gemm_stage(smb + ((kt+1)&1)*GEMM_BUF, Ah, Al, Bh, Bl,
                       rowBase, colBase, (kt+1)*32, tid);
            CP_COMMIT();
            CP_WAIT(1);
        } else {
            CP_WAIT(0);
        }
        __syncthreads();

        const uint32_t bufb = smb + (kt&1)*GEMM_BUF;
        #pragma unroll
        for (int ks = 0; ks < 2; ks++) {
            const uint32_t colB = (uint32_t)((ks*16 + (lane >> 4)*8) * 2);
            unsigned Afh[2][4], Afl[2][4];
            #pragma unroll
            for (int i = 0; i < 2; i++) {
                const uint32_t rowb = (uint32_t)((mw*32 + i*16 + (lane & 15)) * 80);
                LDSM4(Afh[i][0],Afh[i][1],Afh[i][2],Afh[i][3], bufb + rowb + colB);
                LDSM4(Afl[i][0],Afl[i][1],Afl[i][2],Afl[i][3], bufb + 10240 + rowb + colB);
            }
            #pragma unroll
            for (int bt = 0; bt < 4; bt++) {
                const uint32_t rowb = (uint32_t)((nw*64 + bt*16 + (lane & 15)) * 80);
                unsigned bh0,bh1,bh2,bh3, bl0,bl1,bl2,bl3;
                LDSM4(bh0,bh1,bh2,bh3, bufb + 20480 + rowb + colB);
                LDSM4(bl0,bl1,bl2,bl3, bufb + 30720 + rowb + colB);
                #pragma unroll
                for (int i = 0; i < 2; i++) {
                    MMA(acc[i][2*bt],   Afh[i][0],Afh[i][1],Afh[i][2],Afh[i][3], bh0,bh2);
                    MMA(acc[i][2*bt],   Afh[i][0],Afh[i][1],Afh[i][2],Afh[i][3], bl0,bl2);
                    MMA(acc[i][2*bt],   Afl[i][0],Afl[i][1],Afl[i][2],Afl[i][3], bh0,bh2);
                    MMA(acc[i][2*bt+1], Afh[i][0],Afh[i][1],Afh[i][2],Afh[i][3], bh1,bh3);
                    MMA(acc[i][2*bt+1], Afh[i][0],Afh[i][1],Afh[i][2],Afh[i][3], bl1,bl3);
                    MMA(acc[i][2*bt+1], Afl[i][0],Afl[i][1],Afl[i][2],Afl[i][3], bh1,bh3);
                }
            }
        }
        __syncthreads();
    }

    // ---- Epilogue ----
    const int cb = colBase + nw*64;     // 64-aligned -> single (head,typ) block
    if (EPI == 0) {
        const int head = cb / 192;
        const int rem  = cb - head*192;
        const int typ  = rem >> 6;
        const float scale = (typ == 0) ? 0.125f : 1.f;
        __nv_bfloat16* bh_ = (typ == 0) ? g_qh : (typ == 1) ? g_kh : g_vh;
        __nv_bfloat16* bl_ = (typ == 0) ? g_ql : g_kl;     // unused for typ==2
        #pragma unroll
        for (int i = 0; i < 2; i++) {
            #pragma unroll
            for (int half = 0; half < 2; half++) {
                const int row = rowBase + mw*32 + i*16 + g + half*8;
                const int b_ = row >> 11, s_ = row & (SEQ - 1);
                const size_t base = (((size_t)(b_*NHEADS + head))*SEQ + s_) << 6;
                #pragma unroll
                for (int j = 0; j < 8; j++) {
                    const int d = j*8 + t*2;
                    float2 bs = *(const float2*)(bias + cb + d);
                    const float v0 = (acc[i][j][2*half]   + bs.x) * scale;
                    const float v1 = (acc[i][j][2*half+1] + bs.y) * scale;
                    uint32_t h_, l_; split2(v0, v1, h_, l_);
                    *(uint32_t*)(bh_ + base + d) = h_;
                    if (typ < 2) *(uint32_t*)(bl_ + base + d) = l_;
                }
            }
        }
    } else {
        #pragma unroll
        for (int i = 0; i < 2; i++) {
            #pragma unroll
            for (int half = 0; half < 2; half++) {
                const int row = rowBase + mw*32 + i*16 + g + half*8;
                float* dst = Cg + (size_t)row*EMBED + cb;
                #pragma unroll
                for (int j = 0; j < 8; j++) {
                    const int d = j*8 + t*2;
                    float2 bs = *(const float2*)(bias + cb + d);
                    *(float2*)(dst + d) = make_float2(acc[i][j][2*half]   + bs.x,
                                                      acc[i][j][2*half+1] + bs.y);
                }
            }
        }
    }
}

// ===========================================================================
// Flash attention: bf16x3 QK^T, Px2 PV. cp.async double-buffered K/V tiles.
// Dyn smem: Q phase [Qh@0 (18432), Ql@18432]; then K/V buffers:
// buf b @ b*27648: Kh@0(9216) Kl@9216 Vh@18432. Row pitch 144B.
// ===========================================================================
#define FPB       144
#define KV_BUF    27648
#define FLASH_SMEM (2*KV_BUF)   // 55296 (Q phase uses 36864 of it)
#define NT_F      (SEQ/64)

__device__ __forceinline__ void flash_stage(uint32_t sb,
    const __nv_bfloat16* __restrict__ Kh, const __nv_bfloat16* __restrict__ Kl,
    const __nv_bfloat16* __restrict__ Vh, int krow0, int tid)
{
    #pragma unroll
    for (int p = 0; p < 2; p++) {
        const int idx = tid + p*256;            // 0..511
        const int r = idx >> 3;                 // 0..63
        const int c = (idx & 7) * 8;            // elements 0..56
        const size_t go = (size_t)(krow0 + r)*HDIM + c;
        const uint32_t so = (uint32_t)(r*FPB + c*2);
        CP16(sb + so,         Kh + go);
        CP16(sb + 9216 + so,  Kl + go);
        CP16(sb + 18432 + so, Vh + go);
    }
}

__global__ __launch_bounds__(256) void flash_mma_kernel()
{
    extern __shared__ __align__(16) char smc[];
    const uint32_t smb = sptr(smc);

    const int tid  = threadIdx.x;
    const int lane = tid & 31;
    const int warp = tid >> 5;
    const int g    = lane >> 2;
    const int t    = lane & 3;
    const int h    = blockIdx.y;
    const int b    = blockIdx.z;
    const size_t base = (size_t)(b*NHEADS + h)*SEQ*HDIM;
    const size_t qbase = base + (size_t)blockIdx.x*128*HDIM;

    // --- Stage Q hi/lo (pre-scaled, pre-split) via cp.async ---
    #pragma unroll
    for (int p = 0; p < 4; p++) {
        const int idx = tid + p*256;            // 0..1023
        const int r = idx >> 3;                 // 0..127
        const int c = (idx & 7) * 8;
        const size_t go = qbase + (size_t)r*HDIM + c;
        const uint32_t so = (uint32_t)(r*FPB + c*2);
        CP16(smb + so,         g_qh + go);
        CP16(smb + 18432 + so, g_ql + go);
    }
    CP_COMMIT();
    CP_WAIT(0);
    __syncthreads();

    // --- Q fragments to registers ---
    unsigned Qh[4][4], Ql[4][4];
    {
        const uint32_t rowb = (uint32_t)((warp*16 + (lane & 15)) * FPB);
        const uint32_t cbb  = (uint32_t)(((lane >> 4) * 8) * 2);
        #pragma unroll
        for (int ks = 0; ks < 4; ks++) {
            LDSM4(Qh[ks][0],Qh[ks][1],Qh[ks][2],Qh[ks][3], smb + rowb + ks*32 + cbb);
            LDSM4(Ql[ks][0],Ql[ks][1],Ql[ks][2],Ql[ks][3], smb + 18432 + rowb + ks*32 + cbb);
        }
    }
    __syncthreads();   // smem now reusable for K/V buffers

    float Oacc[8][4];
    #pragma unroll
    for (int j = 0; j < 8; j++)
        #pragma unroll
        for (int i = 0; i < 4; i++) Oacc[j][i] = 0.f;
    float m0 = -1e30f, m1 = -1e30f, l0s = 0.f, l1s = 0.f;

    flash_stage(smb, g_kh + base, g_kl + base, g_vh + base, 0, tid);
    CP_COMMIT();

    for (int kt = 0; kt < NT_F; kt++) {
        if (kt + 1 < NT_F) {
            flash_stage(smb + ((kt+1)&1)*KV_BUF, g_kh + base, g_kl + base,
                        g_vh + base, (kt+1)*64, tid);
            CP_COMMIT();
            CP_WAIT(1);
        } else {
            CP_WAIT(0);
        }
        __syncthreads();

        const uint32_t kvb = smb + (kt&1)*KV_BUF;

        // S = (Q/8) K^T  via bf16x3
        float S[8][4];
        #pragma unroll
        for (int j = 0; j < 8; j++)
            #pragma unroll
            for (int i = 0; i < 4; i++) S[j][i] = 0.f;

        #pragma unroll
        for (int ks = 0; ks < 4; ks++) {
            #pragma unroll
            for (int nb = 0; nb < 4; nb++) {
                const uint32_t rowb = (uint32_t)((nb*16 + (lane & 15)) * FPB);
                const uint32_t colb = (uint32_t)((ks*16 + (lane >> 4)*8) * 2);
                unsigned kh0,kh1,kh2,kh3, kl0,kl1,kl2,kl3;
                LDSM4(kh0,kh1,kh2,kh3, kvb + rowb + colb);
                LDSM4(kl0,kl1,kl2,kl3, kvb + 9216 + rowb + colb);
                MMA(S[2*nb],   Qh[ks][0],Qh[ks][1],Qh[ks][2],Qh[ks][3], kh0,kh2);
                MMA(S[2*nb],   Qh[ks][0],Qh[ks][1],Qh[ks][2],Qh[ks][3], kl0,kl2);
                MMA(S[2*nb],   Ql[ks][0],Ql[ks][1],Ql[ks][2],Ql[ks][3], kh0,kh2);
                MMA(S[2*nb+1], Qh[ks][0],Qh[ks][1],Qh[ks][2],Qh[ks][3], kh1,kh3);
                MMA(S[2*nb+1], Qh[ks][0],Qh[ks][1],Qh[ks][2],Qh[ks][3], kl1,kl3);
                MMA(S[2*nb+1], Ql[ks][0],Ql[ks][1],Ql[ks][2],Ql[ks][3], kh1,kh3);
            }
        }

        // Online softmax
        float mx0 = -1e30f, mx1 = -1e30f;
        #pragma unroll
        for (int j = 0; j < 8; j++) {
            mx0 = fmaxf(mx0, fmaxf(S[j][0], S[j][1]));
            mx1 = fmaxf(mx1, fmaxf(S[j][2], S[j][3]));
        }
        mx0 = fmaxf(mx0, __shfl_xor_sync(0xffffffffu, mx0, 1));
        mx0 = fmaxf(mx0, __shfl_xor_sync(0xffffffffu, mx0, 2));
        mx1 = fmaxf(mx1, __shfl_xor_sync(0xffffffffu, mx1, 1));
        mx1 = fmaxf(mx1, __shfl_xor_sync(0xffffffffu, mx1, 2));
        const float mn0 = fmaxf(m0, mx0);
        const float mn1 = fmaxf(m1, mx1);

        float sum0 = 0.f, sum1 = 0.f;
        #pragma unroll
        for (int j = 0; j < 8; j++) {
            S[j][0] = __expf(S[j][0] - mn0); sum0 += S[j][0];
            S[j][1] = __expf(S[j][1] - mn0); sum0 += S[j][1];
            S[j][2] = __expf(S[j][2] - mn1); sum1 += S[j][2];
            S[j][3] = __expf(S[j][3] - mn1); sum1 += S[j][3];
        }
        sum0 += __shfl_xor_sync(0xffffffffu, sum0, 1);
        sum0 += __shfl_xor_sync(0xffffffffu, sum0, 2);
        sum1 += __shfl_xor_sync(0xffffffffu, sum1, 1);
        sum1 += __shfl_xor_sync(0xffffffffu, sum1, 2);

        const float sc0 = __expf(m0 - mn0);
        const float sc1 = __expf(m1 - mn1);
        l0s = l0s*sc0 + sum0;
        l1s = l1s*sc1 + sum1;
        m0 = mn0; m1 = mn1;
        #pragma unroll
        for (int j = 0; j < 8; j++) {
            Oacc[j][0] *= sc0; Oacc[j][1] *= sc0;
            Oacc[j][2] *= sc1; Oacc[j][3] *= sc1;
        }

        // P hi + residual lo (Px2)
        unsigned Ph[4][4], Pl[4][4];
        #pragma unroll
        for (int ks = 0; ks < 4; ks++) {
            #pragma unroll
            for (int q = 0; q < 2; q++) {
                const int j = 2*ks + q;
                uint32_t h01, l01, h23, l23;
                split2(S[j][0], S[j][1], h01, l01);
                split2(S[j][2], S[j][3], h23, l23);
                Ph[ks][2*q] = h01; Ph[ks][2*q+1] = h23;
                Pl[ks][2*q] = l01; Pl[ks][2*q+1] = l23;
            }
        }

        // O += (Ph + Pl) V
        #pragma unroll
        for (int ks = 0; ks < 4; ks++) {
            #pragma unroll
            for (int nb = 0; nb < 4; nb++) {
                const uint32_t rowb = (uint32_t)((ks*16 + (lane & 15)) * FPB);
                const uint32_t colb = (uint32_t)((nb*16 + (lane >> 4)*8) * 2);
                unsigned v0,v1,v2,v3;
                LDSM4T(v0,v1,v2,v3, kvb + 18432 + rowb + colb);
                MMA(Oacc[2*nb],   Ph[ks][0],Ph[ks][1],Ph[ks][2],Ph[ks][3], v0,v1);
                MMA(Oacc[2*nb],   Pl[ks][0],Pl[ks][1],Pl[ks][2],Pl[ks][3], v0,v1);
                MMA(Oacc[2*nb+1], Ph[ks][0],Ph[ks][1],Ph[ks][2],Ph[ks][3], v2,v3);
                MMA(Oacc[2*nb+1], Pl[ks][0],Pl[ks][1],Pl[ks][2],Pl[ks][3], v2,v3);
            }
        }
        __syncthreads();
    }

    // Epilogue: normalize + write g_attn as bf16 hi/lo [B,S,E]
    const float inv0 = 1.f / l0s;
    const float inv1 = 1.f / l1s;
    const int q = blockIdx.x*128 + warp*16;
    const size_t rbase = ((size_t)b*SEQ + q)*EMBED + h*HDIM;
    #pragma unroll
    for (int j = 0; j < 8; j++) {
        const int col = j*8 + t*2;
        uint32_t h_, l_;
        split2(Oacc[j][0]*inv0, Oacc[j][1]*inv0, h_, l_);
        *(uint32_t*)(g_ah + rbase + (size_t)g*EMBED + col) = h_;
        *(uint32_t*)(g_al + rbase + (size_t)g*EMBED + col) = l_;
        split2(Oacc[j][2]*inv1, Oacc[j][3]*inv1, h_, l_);
        *(uint32_t*)(g_ah + rbase + (size_t)(g+8)*EMBED + col) = h_;
        *(uint32_t*)(g_al + rbase + (size_t)(g+8)*EMBED + col) = l_;
    }
}

// ===========================================================================
extern "C" void kernel_launch(void* const* d_in, const int* in_sizes, int n_in,
                              void* d_out, int out_size)
{
    const float* x     = (const float*)d_in[0];
    const float* qkv_w = (const float*)d_in[1];
    const float* qkv_b = (const float*)d_in[2];
    const float* out_w = (const float*)d_in[3];
    const float* out_b = (const float*)d_in[4];
    float* out = (float*)d_out;

    cudaFuncSetAttribute(hmma_gemm_kernel<0>,
                         cudaFuncAttributeMaxDynamicSharedMemorySize, GEMM_SMEM);
    cudaFuncSetAttribute(hmma_gemm_kernel<1>,
                         cudaFuncAttributeMaxDynamicSharedMemorySize, GEMM_SMEM);
    cudaFuncSetAttribute(flash_mma_kernel,
                         cudaFuncAttributeMaxDynamicSharedMemorySize, FLASH_SMEM);

    conv_kernel<<<N_X4/256, 256>>>(qkv_w, out_w, x);
    hmma_gemm_kernel<0><<<dim3(QKVN/128, MTOT/128), 256, GEMM_SMEM>>>(qkv_b, nullptr);
    flash_mma_kernel<<<dim3(SEQ/128, NHEADS, BATCH), 256, FLASH_SMEM>>>();
    hmma_gemm_kernel<1><<<dim3(EMBED/128, MTOT/128), 256, GEMM_SMEM>>>(out_b, out);
}

// round 9
// speedup vs baseline: 6.4309x; 1.3460x over previous
#include <cuda_runtime.h>
#include <cuda_fp16.h>
#include <cstdint>

#define NHEADS 16
#define HDIM   64
#define EMBED  1024
#define BATCH  2
#define SEQ    2048
#define MTOT   (BATCH*SEQ)          // 4096
#define QKVN   (3*EMBED)            // 3072
#define QKV_ELEMS (BATCH*NHEADS*SEQ*HDIM)   // 4194304

// -------- device-global scratch (device-code references only!) -------------
__device__ __half g_xh[MTOT*EMBED],  g_xl[MTOT*EMBED];   // x hi/lo (fp16 split)
__device__ __half g_wq[QKVN*EMBED];                      // qkv_w single fp16
__device__ __half g_wo[EMBED*EMBED];                     // out_w single fp16
__device__ __half g_qh[QKV_ELEMS], g_ql[QKV_ELEMS];      // Q/8 hi/lo [B,H,S,d]
__device__ __half g_k[QKV_ELEMS];                        // K single fp16
__device__ __half g_v[QKV_ELEMS];                        // V single fp16
__device__ __half g_ah[MTOT*EMBED], g_al[MTOT*EMBED];    // attn hi/lo [B,S,E]

// ===========================================================================
// Helpers
// ===========================================================================
__device__ __forceinline__ unsigned sptr(const void* p) {
    return (unsigned)__cvta_generic_to_shared(p);
}
// pack 2 floats into f16x2 {elem0(lo bits)=a, elem1=b}
__device__ __forceinline__ uint32_t cvth2(float a, float b) {
    uint32_t r;
    asm("cvt.rn.f16x2.f32 %0, %1, %2;" : "=r"(r) : "f"(b), "f"(a));
    return r;
}
__device__ __forceinline__ void split2h(float a, float b, uint32_t& hi, uint32_t& lo) {
    hi = cvth2(a, b);
    __half2 h = *(__half2*)&hi;
    float ra = a - __half2float(h.x);
    float rb = b - __half2float(h.y);
    lo = cvth2(ra, rb);
}
__device__ __forceinline__ void split4h(float4 v, uint2& hi, uint2& lo) {
    split2h(v.x, v.y, hi.x, lo.x);
    split2h(v.z, v.w, hi.y, lo.y);
}

#define CP16(SADDR, GPTR) \
    asm volatile("cp.async.cg.shared.global [%0], [%1], 16;" \
        :: "r"((uint32_t)(SADDR)), "l"(GPTR) : "memory")
#define CP_COMMIT() asm volatile("cp.async.commit_group;" ::: "memory")
#define CP_WAIT0()  asm volatile("cp.async.wait_group 0;" ::: "memory")

#define LDSM4(R0,R1,R2,R3,ADDR) \
    asm volatile("ldmatrix.sync.aligned.m8n8.x4.shared.b16 {%0,%1,%2,%3},[%4];" \
        : "=r"(R0),"=r"(R1),"=r"(R2),"=r"(R3) : "r"(ADDR))
#define LDSM4T(R0,R1,R2,R3,ADDR) \
    asm volatile("ldmatrix.sync.aligned.m8n8.x4.trans.shared.b16 {%0,%1,%2,%3},[%4];" \
        : "=r"(R0),"=r"(R1),"=r"(R2),"=r"(R3) : "r"(ADDR))
#define MMAH(D,A0,A1,A2,A3,B0,B1) \
    asm volatile("mma.sync.aligned.m16n8k16.row.col.f32.f16.f16.f32 " \
        "{%0,%1,%2,%3},{%4,%5,%6,%7},{%8,%9},{%0,%1,%2,%3};" \
        : "+f"(D[0]),"+f"(D[1]),"+f"(D[2]),"+f"(D[3]) \
        : "r"(A0),"r"(A1),"r"(A2),"r"(A3),"r"(B0),"r"(B1))

// ===========================================================================
// Pre-convert: x -> fp16 hi/lo; qkv_w, out_w -> single fp16
// ===========================================================================
#define N_QW4 (QKVN*EMBED/4)   // 786432
#define N_OW4 (EMBED*EMBED/4)  // 262144
#define N_X4  (MTOT*EMBED/4)   // 1048576

__global__ __launch_bounds__(256) void conv_kernel(
    const float* __restrict__ qkv_w, const float* __restrict__ out_w,
    const float* __restrict__ x)
{
    const int i = blockIdx.x*256 + threadIdx.x;
    if (i < N_QW4) {
        float4 v = ((const float4*)qkv_w)[i];
        ((uint2*)g_wq)[i] = make_uint2(cvth2(v.x, v.y), cvth2(v.z, v.w));
    }
    if (i < N_OW4) {
        float4 v = ((const float4*)out_w)[i];
        ((uint2*)g_wo)[i] = make_uint2(cvth2(v.x, v.y), cvth2(v.z, v.w));
    }
    if (i < N_X4) {
        uint2 hi, lo;
        split4h(((const float4*)x)[i], hi, lo);
        ((uint2*)g_xh)[i] = hi; ((uint2*)g_xl)[i] = lo;
    }
}

// ===========================================================================
// fp16 asym-x2 GEMM: C[M,N] = A[M,1024] @ B[N,1024]^T (+bias)
// A split hi/lo, B single. CTA 128x128, warp 32x64, K-tile 32.
// Buffer (30720B): Ah@0 Al@10240 B@20480, pitch 80B. 2 buffers.
// EPI=0: scatter Q(hi/lo,*1/8), K(fp16), V(fp16).  EPI=1: fp32 out.
// ===========================================================================
#define GEMM_BUF  30720
#define GEMM_SMEM (2*GEMM_BUF)   // 61440
#define NT_G      (EMBED/32)

__device__ __forceinline__ void gemm_stage(uint32_t sb,
    const __half* __restrict__ Ah, const __half* __restrict__ Al,
    const __half* __restrict__ B, int rowBase, int colBase, int k0, int tid)
{
    #pragma unroll
    for (int p = 0; p < 2; p++) {
        const int idx = tid + p*256;            // 0..511
        const int r = idx >> 2;                 // 0..127
        const int c = (idx & 3) * 8;            // 0,8,16,24
        const uint32_t so = (uint32_t)(r*80 + c*2);
        const size_t ga = (size_t)(rowBase + r)*EMBED + k0 + c;
        CP16(sb + so,         Ah + ga);
        CP16(sb + 10240 + so, Al + ga);
        const size_t gb = (size_t)(colBase + r)*EMBED + k0 + c;
        CP16(sb + 20480 + so, B + gb);
    }
}

template<int EPI>
__global__ __launch_bounds__(256) void hmma_gemm_kernel(
    const float* __restrict__ bias, float* __restrict__ Cg)
{
    extern __shared__ __align__(16) char smc[];
    const uint32_t smb = sptr(smc);

    const __half* Ah = (EPI == 0) ? g_xh : g_ah;
    const __half* Al = (EPI == 0) ? g_xl : g_al;
    const __half* Bp = (EPI == 0) ? g_wq : g_wo;

    const int tid  = threadIdx.x;
    const int lane = tid & 31;
    const int warp = tid >> 5;
    const int mw   = warp & 3;
    const int nw   = warp >> 2;
    const int g    = lane >> 2;
    const int t    = lane & 3;
    const int rowBase = blockIdx.y * 128;
    const int colBase = blockIdx.x * 128;

    float acc[2][8][4];
    #pragma unroll
    for (int i = 0; i < 2; i++)
        #pragma unroll
        for (int j = 0; j < 8; j++)
            #pragma unroll
            for (int c = 0; c < 4; c++) acc[i][j][c] = 0.f;

    gemm_stage(smb, Ah, Al, Bp, rowBase, colBase, 0, tid);
    CP_COMMIT();

    for (int kt = 0; kt < NT_G; kt++) {
        CP_WAIT0();
        __syncthreads();          // tile kt visible; all warps done with buf kt^1
        if (kt + 1 < NT_G) {      // prefetch overlaps compute below
            gemm_stage(smb + ((kt+1)&1)*GEMM_BUF, Ah, Al, Bp,
                       rowBase, colBase, (kt+1)*32, tid);
            CP_COMMIT();
        }
        const uint32_t bufb = smb + (kt&1)*GEMM_BUF;
        #pragma unroll
        for (int ks = 0; ks < 2; ks++) {
            const uint32_t colB = (uint32_t)((ks*16 + (lane >> 4)*8) * 2);
            unsigned Afh[2][4], Afl[2][4];
            #pragma unroll
            for (int i = 0; i < 2; i++) {
                const uint32_t rowb = (uint32_t)((mw*32 + i*16 + (lane & 15)) * 80);
                LDSM4(Afh[i][0],Afh[i][1],Afh[i][2],Afh[i][3], bufb + rowb + colB);
                LDSM4(Afl[i][0],Afl[i][1],Afl[i][2],Afl[i][3], bufb + 10240 + rowb + colB);
            }
            #pragma unroll
            for (int bt = 0; bt < 4; bt++) {
                const uint32_t rowb = (uint32_t)((nw*64 + bt*16 + (lane & 15)) * 80);
                unsigned b0,b1,b2,b3;
                LDSM4(b0,b1,b2,b3, bufb + 20480 + rowb + colB);
                #pragma unroll
                for (int i = 0; i < 2; i++) {
                    MMAH(acc[i][2*bt],   Afh[i][0],Afh[i][1],Afh[i][2],Afh[i][3], b0,b2);
                    MMAH(acc[i][2*bt],   Afl[i][0],Afl[i][1],Afl[i][2],Afl[i][3], b0,b2);
                    MMAH(acc[i][2*bt+1], Afh[i][0],Afh[i][1],Afh[i][2],Afh[i][3], b1,b3);
                    MMAH(acc[i][2*bt+1], Afl[i][0],Afl[i][1],Afl[i][2],Afl[i][3], b1,b3);
                }
            }
        }
    }

    // ---- Epilogue ----
    const int cb = colBase + nw*64;     // 64-aligned -> single (head,typ) block
    if (EPI == 0) {
        const int head = cb / 192;
        const int rem  = cb - head*192;
        const int typ  = rem >> 6;
        __half* sdst = (typ == 1) ? g_k : g_v;
        #pragma unroll
        for (int i = 0; i < 2; i++) {
            #pragma unroll
            for (int half = 0; half < 2; half++) {
                const int row = rowBase + mw*32 + i*16 + g + half*8;
                const int b_ = row >> 11, s_ = row & (SEQ - 1);
                const size_t base = (((size_t)(b_*NHEADS + head))*SEQ + s_) << 6;
                #pragma unroll
                for (int j = 0; j < 8; j++) {
                    const int d = j*8 + t*2;
                    float2 bs = *(const float2*)(bias + cb + d);
                    const float v0 = acc[i][j][2*half]   + bs.x;
                    const float v1 = acc[i][j][2*half+1] + bs.y;
                    if (typ == 0) {
                        uint32_t h_, l_;
                        split2h(v0*0.125f, v1*0.125f, h_, l_);
                        *(uint32_t*)(g_qh + base + d) = h_;
                        *(uint32_t*)(g_ql + base + d) = l_;
                    } else {
                        *(uint32_t*)(sdst + base + d) = cvth2(v0, v1);
                    }
                }
            }
        }
    } else {
        #pragma unroll
        for (int i = 0; i < 2; i++) {
            #pragma unroll
            for (int half = 0; half < 2; half++) {
                const int row = rowBase + mw*32 + i*16 + g + half*8;
                float* dst = Cg + (size_t)row*EMBED + cb;
                #pragma unroll
                for (int j = 0; j < 8; j++) {
                    const int d = j*8 + t*2;
                    float2 bs = *(const float2*)(bias + cb + d);
                    *(float2*)(dst + d) = make_float2(acc[i][j][2*half]   + bs.x,
                                                      acc[i][j][2*half+1] + bs.y);
                }
            }
        }
    }
}

// ===========================================================================
// Flash attention: Qx2 (hi/lo fp16) · K(fp16); Px2 · V(fp16).
// Dyn smem: Q phase [Qh@0, Ql@18432] (pitch 144B); then K/V:
// buf b @ b*18432: K@0 (9216B), V@9216. FLASH_SMEM = 36864.
// ===========================================================================
#define FPB        144
#define KV_BUF     18432
#define FLASH_SMEM 36864
#define NT_F       (SEQ/64)

__device__ __forceinline__ void flash_stage(uint32_t sb,
    const __half* __restrict__ K, const __half* __restrict__ V,
    int krow0, int tid)
{
    #pragma unroll
    for (int p = 0; p < 2; p++) {
        const int idx = tid + p*256;            // 0..511
        const int r = idx >> 3;                 // 0..63
        const int c = (idx & 7) * 8;            // 0..56
        const size_t go = (size_t)(krow0 + r)*HDIM + c;
        const uint32_t so = (uint32_t)(r*FPB + c*2);
        CP16(sb + so,        K + go);
        CP16(sb + 9216 + so, V + go);
    }
}

__global__ __launch_bounds__(256) void flash_mma_kernel()
{
    extern __shared__ __align__(16) char smc[];
    const uint32_t smb = sptr(smc);

    const int tid  = threadIdx.x;
    const int lane = tid & 31;
    const int warp = tid >> 5;
    const int g    = lane >> 2;
    const int t    = lane & 3;
    const int h    = blockIdx.y;
    const int b    = blockIdx.z;
    const size_t base = (size_t)(b*NHEADS + h)*SEQ*HDIM;
    const size_t qbase = base + (size_t)blockIdx.x*128*HDIM;

    // --- Stage Q hi/lo (pre-scaled, pre-split fp16) ---
    #pragma unroll
    for (int p = 0; p < 4; p++) {
        const int idx = tid + p*256;            // 0..1023
        const int r = idx >> 3;                 // 0..127
        const int c = (idx & 7) * 8;
        const size_t go = qbase + (size_t)r*HDIM + c;
        const uint32_t so = (uint32_t)(r*FPB + c*2);
        CP16(smb + so,         g_qh + go);
        CP16(smb + 18432 + so, g_ql + go);
    }
    CP_COMMIT();
    CP_WAIT0();
    __syncthreads();

    // --- Q fragments to registers ---
    unsigned Qh[4][4], Ql[4][4];
    {
        const uint32_t rowb = (uint32_t)((warp*16 + (lane & 15)) * FPB);
        const uint32_t cbb  = (uint32_t)(((lane >> 4) * 8) * 2);
        #pragma unroll
        for (int ks = 0; ks < 4; ks++) {
            LDSM4(Qh[ks][0],Qh[ks][1],Qh[ks][2],Qh[ks][3], smb + rowb + ks*32 + cbb);
            LDSM4(Ql[ks][0],Ql[ks][1],Ql[ks][2],Ql[ks][3], smb + 18432 + rowb + ks*32 + cbb);
        }
    }
    __syncthreads();   // smem now reusable for K/V buffers

    float Oacc[8][4];
    #pragma unroll
    for (int j = 0; j < 8; j++)
        #pragma unroll
        for (int i = 0; i < 4; i++) Oacc[j][i] = 0.f;
    float m0 = -1e30f, m1 = -1e30f, l0s = 0.f, l1s = 0.f;

    flash_stage(smb, g_k + base, g_v + base, 0, tid);
    CP_COMMIT();

    for (int kt = 0; kt < NT_F; kt++) {
        CP_WAIT0();
        __syncthreads();          // tile kt ready; all warps done with buf kt^1
        if (kt + 1 < NT_F) {
            flash_stage(smb + ((kt+1)&1)*KV_BUF, g_k + base, g_v + base,
                        (kt+1)*64, tid);
            CP_COMMIT();
        }
        const uint32_t kvb = smb + (kt&1)*KV_BUF;

        // S = (Q/8) K^T : (Qh + Ql) · K
        float S[8][4];
        #pragma unroll
        for (int j = 0; j < 8; j++)
            #pragma unroll
            for (int i = 0; i < 4; i++) S[j][i] = 0.f;

        #pragma unroll
        for (int ks = 0; ks < 4; ks++) {
            #pragma unroll
            for (int nb = 0; nb < 4; nb++) {
                const uint32_t rowb = (uint32_t)((nb*16 + (lane & 15)) * FPB);
                const uint32_t colb = (uint32_t)((ks*16 + (lane >> 4)*8) * 2);
                unsigned k0,k1,k2,k3;
                LDSM4(k0,k1,k2,k3, kvb + rowb + colb);
                MMAH(S[2*nb],   Qh[ks][0],Qh[ks][1],Qh[ks][2],Qh[ks][3], k0,k2);
                MMAH(S[2*nb],   Ql[ks][0],Ql[ks][1],Ql[ks][2],Ql[ks][3], k0,k2);
                MMAH(S[2*nb+1], Qh[ks][0],Qh[ks][1],Qh[ks][2],Qh[ks][3], k1,k3);
                MMAH(S[2*nb+1], Ql[ks][0],Ql[ks][1],Ql[ks][2],Ql[ks][3], k1,k3);
            }
        }

        // Online softmax
        float mx0 = -1e30f, mx1 = -1e30f;
        #pragma unroll
        for (int j = 0; j < 8; j++) {
            mx0 = fmaxf(mx0, fmaxf(S[j][0], S[j][1]));
            mx1 = fmaxf(mx1, fmaxf(S[j][2], S[j][3]));
        }
        mx0 = fmaxf(mx0, __shfl_xor_sync(0xffffffffu, mx0, 1));
        mx0 = fmaxf(mx0, __shfl_xor_sync(0xffffffffu, mx0, 2));
        mx1 = fmaxf(mx1, __shfl_xor_sync(0xffffffffu, mx1, 1));
        mx1 = fmaxf(mx1, __shfl_xor_sync(0xffffffffu, mx1, 2));
        const float mn0 = fmaxf(m0, mx0);
        const float mn1 = fmaxf(m1, mx1);

        float sum0 = 0.f, sum1 = 0.f;
        #pragma unroll
        for (int j = 0; j < 8; j++) {
            S[j][0] = __expf(S[j][0] - mn0); sum0 += S[j][0];
            S[j][1] = __expf(S[j][1] - mn0); sum0 += S[j][1];
            S[j][2] = __expf(S[j][2] - mn1); sum1 += S[j][2];
            S[j][3] = __expf(S[j][3] - mn1); sum1 += S[j][3];
        }
        sum0 += __shfl_xor_sync(0xffffffffu, sum0, 1);
        sum0 += __shfl_xor_sync(0xffffffffu, sum0, 2);
        sum1 += __shfl_xor_sync(0xffffffffu, sum1, 1);
        sum1 += __shfl_xor_sync(0xffffffffu, sum1, 2);

        const float sc0 = __expf(m0 - mn0);
        const float sc1 = __expf(m1 - mn1);
        l0s = l0s*sc0 + sum0;
        l1s = l1s*sc1 + sum1;
        m0 = mn0; m1 = mn1;
        #pragma unroll
        for (int j = 0; j < 8; j++) {
            Oacc[j][0] *= sc0; Oacc[j][1] *= sc0;
            Oacc[j][2] *= sc1; Oacc[j][3] *= sc1;
        }

        // P split hi/lo fp16
        unsigned Ph[4][4], Pl[4][4];
        #pragma unroll
        for (int ks = 0; ks < 4; ks++) {
            #pragma unroll
            for (int q = 0; q < 2; q++) {
                const int j = 2*ks + q;
                uint32_t h01, l01, h23, l23;
                split2h(S[j][0], S[j][1], h01, l01);
                split2h(S[j][2], S[j][3], h23, l23);
                Ph[ks][2*q] = h01; Ph[ks][2*q+1] = h23;
                Pl[ks][2*q] = l01; Pl[ks][2*q+1] = l23;
            }
        }

        // O += (Ph + Pl) V
        #pragma unroll
        for (int ks = 0; ks < 4; ks++) {
            #pragma unroll
            for (int nb = 0; nb < 4; nb++) {
                const uint32_t rowb = (uint32_t)((ks*16 + (lane & 15)) * FPB);
                const uint32_t colb = (uint32_t)((nb*16 + (lane >> 4)*8) * 2);
                unsigned v0,v1,v2,v3;
                LDSM4T(v0,v1,v2,v3, kvb + 9216 + rowb + colb);
                MMAH(Oacc[2*nb],   Ph[ks][0],Ph[ks][1],Ph[ks][2],Ph[ks][3], v0,v1);
                MMAH(Oacc[2*nb],   Pl[ks][0],Pl[ks][1],Pl[ks][2],Pl[ks][3], v0,v1);
                MMAH(Oacc[2*nb+1], Ph[ks][0],Ph[ks][1],Ph[ks][2],Ph[ks][3], v2,v3);
                MMAH(Oacc[2*nb+1], Pl[ks][0],Pl[ks][1],Pl[ks][2],Pl[ks][3], v2,v3);
            }
        }
    }

    // Epilogue: normalize + write attn as fp16 hi/lo [B,S,E]
    const float inv0 = 1.f / l0s;
    const float inv1 = 1.f / l1s;
    const int q = blockIdx.x*128 + warp*16;
    const size_t rbase = ((size_t)b*SEQ + q)*EMBED + h*HDIM;
    #pragma unroll
    for (int j = 0; j < 8; j++) {
        const int col = j*8 + t*2;
        uint32_t h_, l_;
        split2h(Oacc[j][0]*inv0, Oacc[j][1]*inv0, h_, l_);
        *(uint32_t*)(g_ah + rbase + (size_t)g*EMBED + col) = h_;
        *(uint32_t*)(g_al + rbase + (size_t)g*EMBED + col) = l_;
        split2h(Oacc[j][2]*inv1, Oacc[j][3]*inv1, h_, l_);
        *(uint32_t*)(g_ah + rbase + (size_t)(g+8)*EMBED + col) = h_;
        *(uint32_t*)(g_al + rbase + (size_t)(g+8)*EMBED + col) = l_;
    }
}

// ===========================================================================
extern "C" void kernel_launch(void* const* d_in, const int* in_sizes, int n_in,
                              void* d_out, int out_size)
{
    const float* x     = (const float*)d_in[0];
    const float* qkv_w = (const float*)d_in[1];
    const float* qkv_b = (const float*)d_in[2];
    const float* out_w = (const float*)d_in[3];
    const float* out_b = (const float*)d_in[4];
    float* out = (float*)d_out;

    cudaFuncSetAttribute(hmma_gemm_kernel<0>,
                         cudaFuncAttributeMaxDynamicSharedMemorySize, GEMM_SMEM);
    cudaFuncSetAttribute(hmma_gemm_kernel<1>,
                         cudaFuncAttributeMaxDynamicSharedMemorySize, GEMM_SMEM);
    cudaFuncSetAttribute(flash_mma_kernel,
                         cudaFuncAttributeMaxDynamicSharedMemorySize, FLASH_SMEM);

    conv_kernel<<<N_X4/256, 256>>>(qkv_w, out_w, x);
    hmma_gemm_kernel<0><<<dim3(QKVN/128, MTOT/128), 256, GEMM_SMEM>>>(qkv_b, nullptr);
    flash_mma_kernel<<<dim3(SEQ/128, NHEADS, BATCH), 256, FLASH_SMEM>>>();
    hmma_gemm_kernel<1><<<dim3(EMBED/128, MTOT/128), 256, GEMM_SMEM>>>(out_b, out);
}

// round 10
// speedup vs baseline: 8.0676x; 1.2545x over previous
#include <cuda_runtime.h>
#include <cuda_fp16.h>
#include <cstdint>

#define NHEADS 16
#define HDIM   64
#define EMBED  1024
#define BATCH  2
#define SEQ    2048
#define MTOT   (BATCH*SEQ)          // 4096
#define QKVN   (3*EMBED)            // 3072
#define QKV_ELEMS (BATCH*NHEADS*SEQ*HDIM)   // 4194304

// -------- device-global scratch (device-code references only!) -------------
__device__ __half g_xh[MTOT*EMBED],  g_xl[MTOT*EMBED];   // x hi/lo (fp16 split)
__device__ __half g_wq[QKVN*EMBED];                      // qkv_w single fp16
__device__ __half g_wo[EMBED*EMBED];                     // out_w single fp16
__device__ __half g_qs[QKV_ELEMS];                       // Q/8 single fp16 [B,H,S,d]
__device__ __half g_k[QKV_ELEMS];                        // K single fp16
__device__ __half g_v[QKV_ELEMS];                        // V single fp16
__device__ __half g_ah[MTOT*EMBED], g_al[MTOT*EMBED];    // attn hi/lo [B,S,E]

// ===========================================================================
// Helpers
// ===========================================================================
__device__ __forceinline__ unsigned sptr(const void* p) {
    return (unsigned)__cvta_generic_to_shared(p);
}
// pack 2 floats into f16x2 {elem0(lo bits)=a, elem1=b}
__device__ __forceinline__ uint32_t cvth2(float a, float b) {
    uint32_t r;
    asm("cvt.rn.f16x2.f32 %0, %1, %2;" : "=r"(r) : "f"(b), "f"(a));
    return r;
}
__device__ __forceinline__ void split2h(float a, float b, uint32_t& hi, uint32_t& lo) {
    hi = cvth2(a, b);
    __half2 h = *(__half2*)&hi;
    float ra = a - __half2float(h.x);
    float rb = b - __half2float(h.y);
    lo = cvth2(ra, rb);
}
__device__ __forceinline__ void split4h(float4 v, uint2& hi, uint2& lo) {
    split2h(v.x, v.y, hi.x, lo.x);
    split2h(v.z, v.w, hi.y, lo.y);
}

#define CP16(SADDR, GPTR) \
    asm volatile("cp.async.cg.shared.global [%0], [%1], 16;" \
        :: "r"((uint32_t)(SADDR)), "l"(GPTR) : "memory")
#define CP_COMMIT() asm volatile("cp.async.commit_group;" ::: "memory")
#define CP_WAIT0()  asm volatile("cp.async.wait_group 0;" ::: "memory")

#define LDSM4(R0,R1,R2,R3,ADDR) \
    asm volatile("ldmatrix.sync.aligned.m8n8.x4.shared.b16 {%0,%1,%2,%3},[%4];" \
        : "=r"(R0),"=r"(R1),"=r"(R2),"=r"(R3) : "r"(ADDR))
#define LDSM4T(R0,R1,R2,R3,ADDR) \
    asm volatile("ldmatrix.sync.aligned.m8n8.x4.trans.shared.b16 {%0,%1,%2,%3},[%4];" \
        : "=r"(R0),"=r"(R1),"=r"(R2),"=r"(R3) : "r"(ADDR))
#define MMAH(D,A0,A1,A2,A3,B0,B1) \
    asm volatile("mma.sync.aligned.m16n8k16.row.col.f32.f16.f16.f32 " \
        "{%0,%1,%2,%3},{%4,%5,%6,%7},{%8,%9},{%0,%1,%2,%3};" \
        : "+f"(D[0]),"+f"(D[1]),"+f"(D[2]),"+f"(D[3]) \
        : "r"(A0),"r"(A1),"r"(A2),"r"(A3),"r"(B0),"r"(B1))

// ===========================================================================
// Pre-convert: x -> fp16 hi/lo; qkv_w, out_w -> single fp16
// ===========================================================================
#define N_QW4 (QKVN*EMBED/4)   // 786432
#define N_OW4 (EMBED*EMBED/4)  // 262144
#define N_X4  (MTOT*EMBED/4)   // 1048576

__global__ __launch_bounds__(256) void conv_kernel(
    const float* __restrict__ qkv_w, const float* __restrict__ out_w,
    const float* __restrict__ x)
{
    const int i = blockIdx.x*256 + threadIdx.x;
    if (i < N_QW4) {
        float4 v = ((const float4*)qkv_w)[i];
        ((uint2*)g_wq)[i] = make_uint2(cvth2(v.x, v.y), cvth2(v.z, v.w));
    }
    if (i < N_OW4) {
        float4 v = ((const float4*)out_w)[i];
        ((uint2*)g_wo)[i] = make_uint2(cvth2(v.x, v.y), cvth2(v.z, v.w));
    }
    if (i < N_X4) {
        uint2 hi, lo;
        split4h(((const float4*)x)[i], hi, lo);
        ((uint2*)g_xh)[i] = hi; ((uint2*)g_xl)[i] = lo;
    }
}

// ===========================================================================
// fp16 asym-x2 GEMM: C[M,N] = A[M,1024] @ B[N,1024]^T (+bias)
// A split hi/lo, B single. CTA 128x128, warp 32x64, K-tile 64.
// Buffer (55296B): Ah@0 Al@18432 B@36864, row pitch 144B. 2 buffers.
// EPI=0: scatter Q(fp16,*1/8), K(fp16), V(fp16).  EPI=1: fp32 out.
// ===========================================================================
#define GEMM_BUF  55296
#define GEMM_SMEM (2*GEMM_BUF)   // 110592
#define NT_G      (EMBED/64)     // 16

__device__ __forceinline__ void gemm_stage(uint32_t sb,
    const __half* __restrict__ Ah, const __half* __restrict__ Al,
    const __half* __restrict__ B, int rowBase, int colBase, int k0, int tid)
{
    #pragma unroll
    for (int p = 0; p < 4; p++) {
        const int idx = tid + p*256;            // 0..1023
        const int r = idx >> 3;                 // 0..127
        const int c = (idx & 7) * 8;            // elements 0..56
        const uint32_t so = (uint32_t)(r*144 + c*2);
        const size_t ga = (size_t)(rowBase + r)*EMBED + k0 + c;
        CP16(sb + so,         Ah + ga);
        CP16(sb + 18432 + so, Al + ga);
        const size_t gb = (size_t)(colBase + r)*EMBED + k0 + c;
        CP16(sb + 36864 + so, B + gb);
    }
}

template<int EPI>
__global__ __launch_bounds__(256) void hmma_gemm_kernel(
    const float* __restrict__ bias, float* __restrict__ Cg)
{
    extern __shared__ __align__(16) char smc[];
    const uint32_t smb = sptr(smc);

    const __half* Ah = (EPI == 0) ? g_xh : g_ah;
    const __half* Al = (EPI == 0) ? g_xl : g_al;
    const __half* Bp = (EPI == 0) ? g_wq : g_wo;

    const int tid  = threadIdx.x;
    const int lane = tid & 31;
    const int warp = tid >> 5;
    const int mw   = warp & 3;
    const int nw   = warp >> 2;
    const int g    = lane >> 2;
    const int t    = lane & 3;
    const int rowBase = blockIdx.y * 128;
    const int colBase = blockIdx.x * 128;

    float acc[2][8][4];
    #pragma unroll
    for (int i = 0; i < 2; i++)
        #pragma unroll
        for (int j = 0; j < 8; j++)
            #pragma unroll
            for (int c = 0; c < 4; c++) acc[i][j][c] = 0.f;

    gemm_stage(smb, Ah, Al, Bp, rowBase, colBase, 0, tid);
    CP_COMMIT();

    for (int kt = 0; kt < NT_G; kt++) {
        CP_WAIT0();
        __syncthreads();          // tile kt visible; all warps done with buf kt^1
        if (kt + 1 < NT_G) {      // prefetch overlaps compute below
            gemm_stage(smb + ((kt+1)&1)*GEMM_BUF, Ah, Al, Bp,
                       rowBase, colBase, (kt+1)*64, tid);
            CP_COMMIT();
        }
        const uint32_t bufb = smb + (kt&1)*GEMM_BUF;
        #pragma unroll
        for (int ks = 0; ks < 4; ks++) {
            const uint32_t colB = (uint32_t)((ks*16 + (lane >> 4)*8) * 2);
            unsigned Afh[2][4], Afl[2][4];
            #pragma unroll
            for (int i = 0; i < 2; i++) {
                const uint32_t rowb = (uint32_t)((mw*32 + i*16 + (lane & 15)) * 144);
                LDSM4(Afh[i][0],Afh[i][1],Afh[i][2],Afh[i][3], bufb + rowb + colB);
                LDSM4(Afl[i][0],Afl[i][1],Afl[i][2],Afl[i][3], bufb + 18432 + rowb + colB);
            }
            #pragma unroll
            for (int bt = 0; bt < 4; bt++) {
                const uint32_t rowb = (uint32_t)((nw*64 + bt*16 + (lane & 15)) * 144);
                unsigned b0,b1,b2,b3;
                LDSM4(b0,b1,b2,b3, bufb + 36864 + rowb + colB);
                #pragma unroll
                for (int i = 0; i < 2; i++) {
                    MMAH(acc[i][2*bt],   Afh[i][0],Afh[i][1],Afh[i][2],Afh[i][3], b0,b2);
                    MMAH(acc[i][2*bt],   Afl[i][0],Afl[i][1],Afl[i][2],Afl[i][3], b0,b2);
                    MMAH(acc[i][2*bt+1], Afh[i][0],Afh[i][1],Afh[i][2],Afh[i][3], b1,b3);
                    MMAH(acc[i][2*bt+1], Afl[i][0],Afl[i][1],Afl[i][2],Afl[i][3], b1,b3);
                }
            }
        }
    }

    // ---- Epilogue ----
    const int cb = colBase + nw*64;     // 64-aligned -> single (head,typ) block
    if (EPI == 0) {
        const int head = cb / 192;
        const int rem  = cb - head*192;
        const int typ  = rem >> 6;
        __half* sdst = (typ == 0) ? g_qs : (typ == 1) ? g_k : g_v;
        const float scale = (typ == 0) ? 0.125f : 1.f;
        #pragma unroll
        for (int i = 0; i < 2; i++) {
            #pragma unroll
            for (int half = 0; half < 2; half++) {
                const int row = rowBase + mw*32 + i*16 + g + half*8;
                const int b_ = row >> 11, s_ = row & (SEQ - 1);
                const size_t base = (((size_t)(b_*NHEADS + head))*SEQ + s_) << 6;
                #pragma unroll
                for (int j = 0; j < 8; j++) {
                    const int d = j*8 + t*2;
                    float2 bs = *(const float2*)(bias + cb + d);
                    const float v0 = (acc[i][j][2*half]   + bs.x) * scale;
                    const float v1 = (acc[i][j][2*half+1] + bs.y) * scale;
                    *(uint32_t*)(sdst + base + d) = cvth2(v0, v1);
                }
            }
        }
    } else {
        #pragma unroll
        for (int i = 0; i < 2; i++) {
            #pragma unroll
            for (int half = 0; half < 2; half++) {
                const int row = rowBase + mw*32 + i*16 + g + half*8;
                float* dst = Cg + (size_t)row*EMBED + cb;
                #pragma unroll
                for (int j = 0; j < 8; j++) {
                    const int d = j*8 + t*2;
                    float2 bs = *(const float2*)(bias + cb + d);
                    *(float2*)(dst + d) = make_float2(acc[i][j][2*half]   + bs.x,
                                                      acc[i][j][2*half+1] + bs.y);
                }
            }
        }
    }
}

// ===========================================================================
// Flash attention: single-fp16 Q·K and P·V (64 MMAs per 64-wide K tile).
// Dyn smem: Q phase [Q@0] (pitch 144B, 18432B); then K/V:
// buf b @ b*18432: K@0 (9216B), V@9216. FLASH_SMEM = 36864.
// ===========================================================================
#define FPB        144
#define KV_BUF     18432
#define FLASH_SMEM 36864
#define NT_F       (SEQ/64)

__device__ __forceinline__ void flash_stage(uint32_t sb,
    const __half* __restrict__ K, const __half* __restrict__ V,
    int krow0, int tid)
{
    #pragma unroll
    for (int p = 0; p < 2; p++) {
        const int idx = tid + p*256;            // 0..511
        const int r = idx >> 3;                 // 0..63
        const int c = (idx & 7) * 8;            // 0..56
        const size_t go = (size_t)(krow0 + r)*HDIM + c;
        const uint32_t so = (uint32_t)(r*FPB + c*2);
        CP16(sb + so,        K + go);
        CP16(sb + 9216 + so, V + go);
    }
}

__global__ __launch_bounds__(256) void flash_mma_kernel()
{
    extern __shared__ __align__(16) char smc[];
    const uint32_t smb = sptr(smc);

    const int tid  = threadIdx.x;
    const int lane = tid & 31;
    const int warp = tid >> 5;
    const int g    = lane >> 2;
    const int t    = lane & 3;
    const int h    = blockIdx.y;
    const int b    = blockIdx.z;
    const size_t base = (size_t)(b*NHEADS + h)*SEQ*HDIM;
    const size_t qbase = base + (size_t)blockIdx.x*128*HDIM;

    // --- Stage Q (pre-scaled single fp16) ---
    #pragma unroll
    for (int p = 0; p < 4; p++) {
        const int idx = tid + p*256;            // 0..1023
        const int r = idx >> 3;                 // 0..127
        const int c = (idx & 7) * 8;
        CP16(smb + (uint32_t)(r*FPB + c*2), g_qs + qbase + (size_t)r*HDIM + c);
    }
    CP_COMMIT();
    CP_WAIT0();
    __syncthreads();

    // --- Q fragments to registers ---
    unsigned Qf[4][4];
    {
        const uint32_t rowb = (uint32_t)((warp*16 + (lane & 15)) * FPB);
        const uint32_t cbb  = (uint32_t)(((lane >> 4) * 8) * 2);
        #pragma unroll
        for (int ks = 0; ks < 4; ks++) {
            LDSM4(Qf[ks][0],Qf[ks][1],Qf[ks][2],Qf[ks][3], smb + rowb + ks*32 + cbb);
        }
    }
    __syncthreads();   // smem now reusable for K/V buffers

    float Oacc[8][4];
    #pragma unroll
    for (int j = 0; j < 8; j++)
        #pragma unroll
        for (int i = 0; i < 4; i++) Oacc[j][i] = 0.f;
    float m0 = -1e30f, m1 = -1e30f, l0s = 0.f, l1s = 0.f;

    flash_stage(smb, g_k + base, g_v + base, 0, tid);
    CP_COMMIT();

    for (int kt = 0; kt < NT_F; kt++) {
        CP_WAIT0();
        __syncthreads();          // tile kt ready; all warps done with buf kt^1
        if (kt + 1 < NT_F) {
            flash_stage(smb + ((kt+1)&1)*KV_BUF, g_k + base, g_v + base,
                        (kt+1)*64, tid);
            CP_COMMIT();
        }
        const uint32_t kvb = smb + (kt&1)*KV_BUF;

        // S = (Q/8) K^T
        float S[8][4];
        #pragma unroll
        for (int j = 0; j < 8; j++)
            #pragma unroll
            for (int i = 0; i < 4; i++) S[j][i] = 0.f;

        #pragma unroll
        for (int ks = 0; ks < 4; ks++) {
            #pragma unroll
            for (int nb = 0; nb < 4; nb++) {
                const uint32_t rowb = (uint32_t)((nb*16 + (lane & 15)) * FPB);
                const uint32_t colb = (uint32_t)((ks*16 + (lane >> 4)*8) * 2);
                unsigned k0,k1,k2,k3;
                LDSM4(k0,k1,k2,k3, kvb + rowb + colb);
                MMAH(S[2*nb],   Qf[ks][0],Qf[ks][1],Qf[ks][2],Qf[ks][3], k0,k2);
                MMAH(S[2*nb+1], Qf[ks][0],Qf[ks][1],Qf[ks][2],Qf[ks][3], k1,k3);
            }
        }

        // Online softmax
        float mx0 = -1e30f, mx1 = -1e30f;
        #pragma unroll
        for (int j = 0; j < 8; j++) {
            mx0 = fmaxf(mx0, fmaxf(S[j][0], S[j][1]));
            mx1 = fmaxf(mx1, fmaxf(S[j][2], S[j][3]));
        }
        mx0 = fmaxf(mx0, __shfl_xor_sync(0xffffffffu, mx0, 1));
        mx0 = fmaxf(mx0, __shfl_xor_sync(0xffffffffu, mx0, 2));
        mx1 = fmaxf(mx1, __shfl_xor_sync(0xffffffffu, mx1, 1));
        mx1 = fmaxf(mx1, __shfl_xor_sync(0xffffffffu, mx1, 2));
        const float mn0 = fmaxf(m0, mx0);
        const float mn1 = fmaxf(m1, mx1);

        float sum0 = 0.f, sum1 = 0.f;
        #pragma unroll
        for (int j = 0; j < 8; j++) {
            S[j][0] = __expf(S[j][0] - mn0); sum0 += S[j][0];
            S[j][1] = __expf(S[j][1] - mn0); sum0 += S[j][1];
            S[j][2] = __expf(S[j][2] - mn1); sum1 += S[j][2];
            S[j][3] = __expf(S[j][3] - mn1); sum1 += S[j][3];
        }
        sum0 += __shfl_xor_sync(0xffffffffu, sum0, 1);
        sum0 += __shfl_xor_sync(0xffffffffu, sum0, 2);
        sum1 += __shfl_xor_sync(0xffffffffu, sum1, 1);
        sum1 += __shfl_xor_sync(0xffffffffu, sum1, 2);

        const float sc0 = __expf(m0 - mn0);
        const float sc1 = __expf(m1 - mn1);
        l0s = l0s*sc0 + sum0;
        l1s = l1s*sc1 + sum1;
        m0 = mn0; m1 = mn1;
        #pragma unroll
        for (int j = 0; j < 8; j++) {
            Oacc[j][0] *= sc0; Oacc[j][1] *= sc0;
            Oacc[j][2] *= sc1; Oacc[j][3] *= sc1;
        }

        // P single fp16
        unsigned Pf[4][4];
        #pragma unroll
        for (int ks = 0; ks < 4; ks++) {
            Pf[ks][0] = cvth2(S[2*ks  ][0], S[2*ks  ][1]);
            Pf[ks][1] = cvth2(S[2*ks  ][2], S[2*ks  ][3]);
            Pf[ks][2] = cvth2(S[2*ks+1][0], S[2*ks+1][1]);
            Pf[ks][3] = cvth2(S[2*ks+1][2], S[2*ks+1][3]);
        }

        // O += P V
        #pragma unroll
        for (int ks = 0; ks < 4; ks++) {
            #pragma unroll
            for (int nb = 0; nb < 4; nb++) {
                const uint32_t rowb = (uint32_t)((ks*16 + (lane & 15)) * FPB);
                const uint32_t colb = (uint32_t)((nb*16 + (lane >> 4)*8) * 2);
                unsigned v0,v1,v2,v3;
                LDSM4T(v0,v1,v2,v3, kvb + 9216 + rowb + colb);
                MMAH(Oacc[2*nb],   Pf[ks][0],Pf[ks][1],Pf[ks][2],Pf[ks][3], v0,v1);
                MMAH(Oacc[2*nb+1], Pf[ks][0],Pf[ks][1],Pf[ks][2],Pf[ks][3], v2,v3);
            }
        }
    }

    // Epilogue: normalize + write attn as fp16 hi/lo [B,S,E]
    const float inv0 = 1.f / l0s;
    const float inv1 = 1.f / l1s;
    const int q = blockIdx.x*128 + warp*16;
    const size_t rbase = ((size_t)b*SEQ + q)*EMBED + h*HDIM;
    #pragma unroll
    for (int j = 0; j < 8; j++) {
        const int col = j*8 + t*2;
        uint32_t h_, l_;
        split2h(Oacc[j][0]*inv0, Oacc[j][1]*inv0, h_, l_);
        *(uint32_t*)(g_ah + rbase + (size_t)g*EMBED + col) = h_;
        *(uint32_t*)(g_al + rbase + (size_t)g*EMBED + col) = l_;
        split2h(Oacc[j][2]*inv1, Oacc[j][3]*inv1, h_, l_);
        *(uint32_t*)(g_ah + rbase + (size_t)(g+8)*EMBED + col) = h_;
        *(uint32_t*)(g_al + rbase + (size_t)(g+8)*EMBED + col) = l_;
    }
}

// ===========================================================================
extern "C" void kernel_launch(void* const* d_in, const int* in_sizes, int n_in,
                              void* d_out, int out_size)
{
    const float* x     = (const float*)d_in[0];
    const float* qkv_w = (const float*)d_in[1];
    const float* qkv_b = (const float*)d_in[2];
    const float* out_w = (const float*)d_in[3];
    const float* out_b = (const float*)d_in[4];
    float* out = (float*)d_out;

    cudaFuncSetAttribute(hmma_gemm_kernel<0>,
                         cudaFuncAttributeMaxDynamicSharedMemorySize, GEMM_SMEM);
    cudaFuncSetAttribute(hmma_gemm_kernel<1>,
                         cudaFuncAttributeMaxDynamicSharedMemorySize, GEMM_SMEM);
    cudaFuncSetAttribute(flash_mma_kernel,
                         cudaFuncAttributeMaxDynamicSharedMemorySize, FLASH_SMEM);

    conv_kernel<<<N_X4/256, 256>>>(qkv_w, out_w, x);
    hmma_gemm_kernel<0><<<dim3(QKVN/128, MTOT/128), 256, GEMM_SMEM>>>(qkv_b, nullptr);
    flash_mma_kernel<<<dim3(SEQ/128, NHEADS, BATCH), 256, FLASH_SMEM>>>();
    hmma_gemm_kernel<1><<<dim3(EMBED/128, MTOT/128), 256, GEMM_SMEM>>>(out_b, out);
}

// round 11
// speedup vs baseline: 11.1319x; 1.3798x over previous
#include <cuda_runtime.h>
#include <cuda_fp16.h>
#include <cstdint>

#define NHEADS 16
#define HDIM   64
#define EMBED  1024
#define BATCH  2
#define SEQ    2048
#define MTOT   (BATCH*SEQ)          // 4096
#define QKVN   (3*EMBED)            // 3072
#define QKV_ELEMS (BATCH*NHEADS*SEQ*HDIM)   // 4194304

// -------- device-global scratch (device-code references only!) -------------
__device__ __half g_x[MTOT*EMBED];        // x single fp16
__device__ __half g_wq[QKVN*EMBED];       // qkv_w single fp16
__device__ __half g_wo[EMBED*EMBED];      // out_w single fp16
__device__ __half g_qs[QKV_ELEMS];        // Q/8 single fp16 [B,H,S,d]
__device__ __half g_k[QKV_ELEMS];         // K single fp16
__device__ __half g_v[QKV_ELEMS];         // V single fp16
__device__ __half g_a[MTOT*EMBED];        // attn single fp16 [B,S,E]

// ===========================================================================
// Helpers
// ===========================================================================
__device__ __forceinline__ unsigned sptr(const void* p) {
    return (unsigned)__cvta_generic_to_shared(p);
}
// pack 2 floats into f16x2 {elem0(lo bits)=a, elem1=b}
__device__ __forceinline__ uint32_t cvth2(float a, float b) {
    uint32_t r;
    asm("cvt.rn.f16x2.f32 %0, %1, %2;" : "=r"(r) : "f"(b), "f"(a));
    return r;
}

#define CP16(SADDR, GPTR) \
    asm volatile("cp.async.cg.shared.global [%0], [%1], 16;" \
        :: "r"((uint32_t)(SADDR)), "l"(GPTR) : "memory")
#define CP_COMMIT() asm volatile("cp.async.commit_group;" ::: "memory")
#define CP_WAIT0()  asm volatile("cp.async.wait_group 0;" ::: "memory")

#define LDSM4(R0,R1,R2,R3,ADDR) \
    asm volatile("ldmatrix.sync.aligned.m8n8.x4.shared.b16 {%0,%1,%2,%3},[%4];" \
        : "=r"(R0),"=r"(R1),"=r"(R2),"=r"(R3) : "r"(ADDR))
#define LDSM4T(R0,R1,R2,R3,ADDR) \
    asm volatile("ldmatrix.sync.aligned.m8n8.x4.trans.shared.b16 {%0,%1,%2,%3},[%4];" \
        : "=r"(R0),"=r"(R1),"=r"(R2),"=r"(R3) : "r"(ADDR))
#define MMAH(D,A0,A1,A2,A3,B0,B1) \
    asm volatile("mma.sync.aligned.m16n8k16.row.col.f32.f16.f16.f32 " \
        "{%0,%1,%2,%3},{%4,%5,%6,%7},{%8,%9},{%0,%1,%2,%3};" \
        : "+f"(D[0]),"+f"(D[1]),"+f"(D[2]),"+f"(D[3]) \
        : "r"(A0),"r"(A1),"r"(A2),"r"(A3),"r"(B0),"r"(B1))

// ===========================================================================
// Pre-convert: x, qkv_w, out_w -> single fp16
// ===========================================================================
#define N_QW4 (QKVN*EMBED/4)   // 786432
#define N_OW4 (EMBED*EMBED/4)  // 262144
#define N_X4  (MTOT*EMBED/4)   // 1048576

__global__ __launch_bounds__(256) void conv_kernel(
    const float* __restrict__ qkv_w, const float* __restrict__ out_w,
    const float* __restrict__ x)
{
    const int i = blockIdx.x*256 + threadIdx.x;
    if (i < N_QW4) {
        float4 v = ((const float4*)qkv_w)[i];
        ((uint2*)g_wq)[i] = make_uint2(cvth2(v.x, v.y), cvth2(v.z, v.w));
    }
    if (i < N_OW4) {
        float4 v = ((const float4*)out_w)[i];
        ((uint2*)g_wo)[i] = make_uint2(cvth2(v.x, v.y), cvth2(v.z, v.w));
    }
    if (i < N_X4) {
        float4 v = ((const float4*)x)[i];
        ((uint2*)g_x)[i] = make_uint2(cvth2(v.x, v.y), cvth2(v.z, v.w));
    }
}

// ===========================================================================
// fp16 GEMM: C[M,N] = A[M,1024] @ B[N,1024]^T (+bias)
// Single fp16 both operands. CTA 128x128, warp 32x64, K-tile 64.
// Buffer (36864B): A@0 B@18432, row pitch 144B. 2 buffers (73728B dyn smem).
// EPI=0: scatter Q(fp16,*1/8), K(fp16), V(fp16).  EPI=1: fp32 out.
// ===========================================================================
#define GEMM_BUF  36864
#define GEMM_SMEM (2*GEMM_BUF)   // 73728
#define NT_G      (EMBED/64)     // 16

__device__ __forceinline__ void gemm_stage(uint32_t sb,
    const __half* __restrict__ A, const __half* __restrict__ B,
    int rowBase, int colBase, int k0, int tid)
{
    #pragma unroll
    for (int p = 0; p < 4; p++) {
        const int idx = tid + p*256;            // 0..1023
        const int r = idx >> 3;                 // 0..127
        const int c = (idx & 7) * 8;            // elements 0..56
        const uint32_t so = (uint32_t)(r*144 + c*2);
        CP16(sb + so,         A + (size_t)(rowBase + r)*EMBED + k0 + c);
        CP16(sb + 18432 + so, B + (size_t)(colBase + r)*EMBED + k0 + c);
    }
}

template<int EPI>
__global__ __launch_bounds__(256) void hmma_gemm_kernel(
    const float* __restrict__ bias, float* __restrict__ Cg)
{
    extern __shared__ __align__(16) char smc[];
    const uint32_t smb = sptr(smc);

    const __half* Ap = (EPI == 0) ? g_x  : g_a;
    const __half* Bp = (EPI == 0) ? g_wq : g_wo;

    const int tid  = threadIdx.x;
    const int lane = tid & 31;
    const int warp = tid >> 5;
    const int mw   = warp & 3;
    const int nw   = warp >> 2;
    const int g    = lane >> 2;
    const int t    = lane & 3;
    const int rowBase = blockIdx.y * 128;
    const int colBase = blockIdx.x * 128;

    float acc[2][8][4];
    #pragma unroll
    for (int i = 0; i < 2; i++)
        #pragma unroll
        for (int j = 0; j < 8; j++)
            #pragma unroll
            for (int c = 0; c < 4; c++) acc[i][j][c] = 0.f;

    gemm_stage(smb, Ap, Bp, rowBase, colBase, 0, tid);
    CP_COMMIT();

    for (int kt = 0; kt < NT_G; kt++) {
        CP_WAIT0();
        __syncthreads();          // tile kt visible; all warps done with buf kt^1
        if (kt + 1 < NT_G) {      // prefetch overlaps compute below
            gemm_stage(smb + ((kt+1)&1)*GEMM_BUF, Ap, Bp,
                       rowBase, colBase, (kt+1)*64, tid);
            CP_COMMIT();
        }
        const uint32_t bufb = smb + (kt&1)*GEMM_BUF;
        #pragma unroll
        for (int ks = 0; ks < 4; ks++) {
            const uint32_t colB = (uint32_t)((ks*16 + (lane >> 4)*8) * 2);
            unsigned Af[2][4];
            #pragma unroll
            for (int i = 0; i < 2; i++) {
                const uint32_t rowb = (uint32_t)((mw*32 + i*16 + (lane & 15)) * 144);
                LDSM4(Af[i][0],Af[i][1],Af[i][2],Af[i][3], bufb + rowb + colB);
            }
            #pragma unroll
            for (int bt = 0; bt < 4; bt++) {
                const uint32_t rowb = (uint32_t)((nw*64 + bt*16 + (lane & 15)) * 144);
                unsigned b0,b1,b2,b3;
                LDSM4(b0,b1,b2,b3, bufb + 18432 + rowb + colB);
                #pragma unroll
                for (int i = 0; i < 2; i++) {
                    MMAH(acc[i][2*bt],   Af[i][0],Af[i][1],Af[i][2],Af[i][3], b0,b2);
                    MMAH(acc[i][2*bt+1], Af[i][0],Af[i][1],Af[i][2],Af[i][3], b1,b3);
                }
            }
        }
    }

    // ---- Epilogue ----
    const int cb = colBase + nw*64;     // 64-aligned -> single (head,typ) block
    if (EPI == 0) {
        const int head = cb / 192;
        const int rem  = cb - head*192;
        const int typ  = rem >> 6;
        __half* sdst = (typ == 0) ? g_qs : (typ == 1) ? g_k : g_v;
        const float scale = (typ == 0) ? 0.125f : 1.f;
        #pragma unroll
        for (int i = 0; i < 2; i++) {
            #pragma unroll
            for (int half = 0; half < 2; half++) {
                const int row = rowBase + mw*32 + i*16 + g + half*8;
                const int b_ = row >> 11, s_ = row & (SEQ - 1);
                const size_t base = (((size_t)(b_*NHEADS + head))*SEQ + s_) << 6;
                #pragma unroll
                for (int j = 0; j < 8; j++) {
                    const int d = j*8 + t*2;
                    float2 bs = *(const float2*)(bias + cb + d);
                    const float v0 = (acc[i][j][2*half]   + bs.x) * scale;
                    const float v1 = (acc[i][j][2*half+1] + bs.y) * scale;
                    *(uint32_t*)(sdst + base + d) = cvth2(v0, v1);
                }
            }
        }
    } else {
        #pragma unroll
        for (int i = 0; i < 2; i++) {
            #pragma unroll
            for (int half = 0; half < 2; half++) {
                const int row = rowBase + mw*32 + i*16 + g + half*8;
                float* dst = Cg + (size_t)row*EMBED + cb;
                #pragma unroll
                for (int j = 0; j < 8; j++) {
                    const int d = j*8 + t*2;
                    float2 bs = *(const float2*)(bias + cb + d);
                    *(float2*)(dst + d) = make_float2(acc[i][j][2*half]   + bs.x,
                                                      acc[i][j][2*half+1] + bs.y);
                }
            }
        }
    }
}

// ===========================================================================
// Flash attention: single-fp16 Q·K and P·V (64 MMAs per 64-wide K tile).
// Dyn smem: Q phase [Q@0] (pitch 144B, 18432B); then K/V:
// buf b @ b*18432: K@0 (9216B), V@9216. FLASH_SMEM = 36864.
// ===========================================================================
#define FPB        144
#define KV_BUF     18432
#define FLASH_SMEM 36864
#define NT_F       (SEQ/64)

__device__ __forceinline__ void flash_stage(uint32_t sb,
    const __half* __restrict__ K, const __half* __restrict__ V,
    int krow0, int tid)
{
    #pragma unroll
    for (int p = 0; p < 2; p++) {
        const int idx = tid + p*256;            // 0..511
        const int r = idx >> 3;                 // 0..63
        const int c = (idx & 7) * 8;            // 0..56
        const size_t go = (size_t)(krow0 + r)*HDIM + c;
        const uint32_t so = (uint32_t)(r*FPB + c*2);
        CP16(sb + so,        K + go);
        CP16(sb + 9216 + so, V + go);
    }
}

__global__ __launch_bounds__(256) void flash_mma_kernel()
{
    extern __shared__ __align__(16) char smc[];
    const uint32_t smb = sptr(smc);

    const int tid  = threadIdx.x;
    const int lane = tid & 31;
    const int warp = tid >> 5;
    const int g    = lane >> 2;
    const int t    = lane & 3;
    const int h    = blockIdx.y;
    const int b    = blockIdx.z;
    const size_t base = (size_t)(b*NHEADS + h)*SEQ*HDIM;
    const size_t qbase = base + (size_t)blockIdx.x*128*HDIM;

    // --- Stage Q (pre-scaled single fp16) ---
    #pragma unroll
    for (int p = 0; p < 4; p++) {
        const int idx = tid + p*256;            // 0..1023
        const int r = idx >> 3;                 // 0..127
        const int c = (idx & 7) * 8;
        CP16(smb + (uint32_t)(r*FPB + c*2), g_qs + qbase + (size_t)r*HDIM + c);
    }
    CP_COMMIT();
    CP_WAIT0();
    __syncthreads();

    // --- Q fragments to registers ---
    unsigned Qf[4][4];
    {
        const uint32_t rowb = (uint32_t)((warp*16 + (lane & 15)) * FPB);
        const uint32_t cbb  = (uint32_t)(((lane >> 4) * 8) * 2);
        #pragma unroll
        for (int ks = 0; ks < 4; ks++) {
            LDSM4(Qf[ks][0],Qf[ks][1],Qf[ks][2],Qf[ks][3], smb + rowb + ks*32 + cbb);
        }
    }
    __syncthreads();   // smem now reusable for K/V buffers

    float Oacc[8][4];
    #pragma unroll
    for (int j = 0; j < 8; j++)
        #pragma unroll
        for (int i = 0; i < 4; i++) Oacc[j][i] = 0.f;
    float m0 = -1e30f, m1 = -1e30f, l0s = 0.f, l1s = 0.f;

    flash_stage(smb, g_k + base, g_v + base, 0, tid);
    CP_COMMIT();

    for (int kt = 0; kt < NT_F; kt++) {
        CP_WAIT0();
        __syncthreads();          // tile kt ready; all warps done with buf kt^1
        if (kt + 1 < NT_F) {
            flash_stage(smb + ((kt+1)&1)*KV_BUF, g_k + base, g_v + base,
                        (kt+1)*64, tid);
            CP_COMMIT();
        }
        const uint32_t kvb = smb + (kt&1)*KV_BUF;

        // S = (Q/8) K^T
        float S[8][4];
        #pragma unroll
        for (int j = 0; j < 8; j++)
            #pragma unroll
            for (int i = 0; i < 4; i++) S[j][i] = 0.f;

        #pragma unroll
        for (int ks = 0; ks < 4; ks++) {
            #pragma unroll
            for (int nb = 0; nb < 4; nb++) {
                const uint32_t rowb = (uint32_t)((nb*16 + (lane & 15)) * FPB);
                const uint32_t colb = (uint32_t)((ks*16 + (lane >> 4)*8) * 2);
                unsigned k0,k1,k2,k3;
                LDSM4(k0,k1,k2,k3, kvb + rowb + colb);
                MMAH(S[2*nb],   Qf[ks][0],Qf[ks][1],Qf[ks][2],Qf[ks][3], k0,k2);
                MMAH(S[2*nb+1], Qf[ks][0],Qf[ks][1],Qf[ks][2],Qf[ks][3], k1,k3);
            }
        }

        // Online softmax
        float mx0 = -1e30f, mx1 = -1e30f;
        #pragma unroll
        for (int j = 0; j < 8; j++) {
            mx0 = fmaxf(mx0, fmaxf(S[j][0], S[j][1]));
            mx1 = fmaxf(mx1, fmaxf(S[j][2], S[j][3]));
        }
        mx0 = fmaxf(mx0, __shfl_xor_sync(0xffffffffu, mx0, 1));
        mx0 = fmaxf(mx0, __shfl_xor_sync(0xffffffffu, mx0, 2));
        mx1 = fmaxf(mx1, __shfl_xor_sync(0xffffffffu, mx1, 1));
        mx1 = fmaxf(mx1, __shfl_xor_sync(0xffffffffu, mx1, 2));
        const float mn0 = fmaxf(m0, mx0);
        const float mn1 = fmaxf(m1, mx1);

        float sum0 = 0.f, sum1 = 0.f;
        #pragma unroll
        for (int j = 0; j < 8; j++) {
            S[j][0] = __expf(S[j][0] - mn0); sum0 += S[j][0];
            S[j][1] = __expf(S[j][1] - mn0); sum0 += S[j][1];
            S[j][2] = __expf(S[j][2] - mn1); sum1 += S[j][2];
            S[j][3] = __expf(S[j][3] - mn1); sum1 += S[j][3];
        }
        sum0 += __shfl_xor_sync(0xffffffffu, sum0, 1);
        sum0 += __shfl_xor_sync(0xffffffffu, sum0, 2);
        sum1 += __shfl_xor_sync(0xffffffffu, sum1, 1);
        sum1 += __shfl_xor_sync(0xffffffffu, sum1, 2);

        const float sc0 = __expf(m0 - mn0);
        const float sc1 = __expf(m1 - mn1);
        l0s = l0s*sc0 + sum0;
        l1s = l1s*sc1 + sum1;
        m0 = mn0; m1 = mn1;
        #pragma unroll
        for (int j = 0; j < 8; j++) {
            Oacc[j][0] *= sc0; Oacc[j][1] *= sc0;
            Oacc[j][2] *= sc1; Oacc[j][3] *= sc1;
        }

        // P single fp16
        unsigned Pf[4][4];
        #pragma unroll
        for (int ks = 0; ks < 4; ks++) {
            Pf[ks][0] = cvth2(S[2*ks  ][0], S[2*ks  ][1]);
            Pf[ks][1] = cvth2(S[2*ks  ][2], S[2*ks  ][3]);
            Pf[ks][2] = cvth2(S[2*ks+1][0], S[2*ks+1][1]);
            Pf[ks][3] = cvth2(S[2*ks+1][2], S[2*ks+1][3]);
        }

        // O += P V
        #pragma unroll
        for (int ks = 0; ks < 4; ks++) {
            #pragma unroll
            for (int nb = 0; nb < 4; nb++) {
                const uint32_t rowb = (uint32_t)((ks*16 + (lane & 15)) * FPB);
                const uint32_t colb = (uint32_t)((nb*16 + (lane >> 4)*8) * 2);
                unsigned v0,v1,v2,v3;
                LDSM4T(v0,v1,v2,v3, kvb + 9216 + rowb + colb);
                MMAH(Oacc[2*nb],   Pf[ks][0],Pf[ks][1],Pf[ks][2],Pf[ks][3], v0,v1);
                MMAH(Oacc[2*nb+1], Pf[ks][0],Pf[ks][1],Pf[ks][2],Pf[ks][3], v2,v3);
            }
        }
    }

    // Epilogue: normalize + write attn single fp16 [B,S,E]
    const float inv0 = 1.f / l0s;
    const float inv1 = 1.f / l1s;
    const int q = blockIdx.x*128 + warp*16;
    const size_t rbase = ((size_t)b*SEQ + q)*EMBED + h*HDIM;
    #pragma unroll
    for (int j = 0; j < 8; j++) {
        const int col = j*8 + t*2;
        *(uint32_t*)(g_a + rbase + (size_t)g*EMBED + col) =
            cvth2(Oacc[j][0]*inv0, Oacc[j][1]*inv0);
        *(uint32_t*)(g_a + rbase + (size_t)(g+8)*EMBED + col) =
            cvth2(Oacc[j][2]*inv1, Oacc[j][3]*inv1);
    }
}

// ===========================================================================
extern "C" void kernel_launch(void* const* d_in, const int* in_sizes, int n_in,
                              void* d_out, int out_size)
{
    const float* x     = (const float*)d_in[0];
    const float* qkv_w = (const float*)d_in[1];
    const float* qkv_b = (const float*)d_in[2];
    const float* out_w = (const float*)d_in[3];
    const float* out_b = (const float*)d_in[4];
    float* out = (float*)d_out;

    cudaFuncSetAttribute(hmma_gemm_kernel<0>,
                         cudaFuncAttributeMaxDynamicSharedMemorySize, GEMM_SMEM);
    cudaFuncSetAttribute(hmma_gemm_kernel<1>,
                         cudaFuncAttributeMaxDynamicSharedMemorySize, GEMM_SMEM);
    cudaFuncSetAttribute(flash_mma_kernel,
                         cudaFuncAttributeMaxDynamicSharedMemorySize, FLASH_SMEM);

    conv_kernel<<<N_X4/256, 256>>>(qkv_w, out_w, x);
    hmma_gemm_kernel<0><<<dim3(QKVN/128, MTOT/128), 256, GEMM_SMEM>>>(qkv_b, nullptr);
    flash_mma_kernel<<<dim3(SEQ/128, NHEADS, BATCH), 256, FLASH_SMEM>>>();
    hmma_gemm_kernel<1><<<dim3(EMBED/128, MTOT/128), 256, GEMM_SMEM>>>(out_b, out);
}

// round 12
// speedup vs baseline: 11.4455x; 1.0282x over previous
#include <cuda_runtime.h>
#include <cuda_fp16.h>
#include <cstdint>

#define NHEADS 16
#define HDIM   64
#define EMBED  1024
#define BATCH  2
#define SEQ    2048
#define MTOT   (BATCH*SEQ)          // 4096
#define QKVN   (3*EMBED)            // 3072
#define QKV_ELEMS (BATCH*NHEADS*SEQ*HDIM)   // 4194304

// -------- device-global scratch (device-code references only!) -------------
__device__ __half g_x[MTOT*EMBED];        // x single fp16
__device__ __half g_wq[QKVN*EMBED];       // qkv_w single fp16
__device__ __half g_wo[EMBED*EMBED];      // out_w single fp16
__device__ __half g_qs[QKV_ELEMS];        // Q/8 single fp16 [B,H,S,d]
__device__ __half g_k[QKV_ELEMS];         // K single fp16
__device__ __half g_v[QKV_ELEMS];         // V single fp16
__device__ __half g_a[MTOT*EMBED];        // attn single fp16 [B,S,E]

// ===========================================================================
// Helpers
// ===========================================================================
__device__ __forceinline__ unsigned sptr(const void* p) {
    return (unsigned)__cvta_generic_to_shared(p);
}
// pack 2 floats into f16x2 {elem0(lo bits)=a, elem1=b}
__device__ __forceinline__ uint32_t cvth2(float a, float b) {
    uint32_t r;
    asm("cvt.rn.f16x2.f32 %0, %1, %2;" : "=r"(r) : "f"(b), "f"(a));
    return r;
}

#define CP16(SADDR, GPTR) \
    asm volatile("cp.async.cg.shared.global [%0], [%1], 16;" \
        :: "r"((uint32_t)(SADDR)), "l"(GPTR) : "memory")
#define CP_COMMIT() asm volatile("cp.async.commit_group;" ::: "memory")
#define CP_WAIT0()  asm volatile("cp.async.wait_group 0;" ::: "memory")

#define LDSM4(R0,R1,R2,R3,ADDR) \
    asm volatile("ldmatrix.sync.aligned.m8n8.x4.shared.b16 {%0,%1,%2,%3},[%4];" \
        : "=r"(R0),"=r"(R1),"=r"(R2),"=r"(R3) : "r"(ADDR))
#define LDSM4T(R0,R1,R2,R3,ADDR) \
    asm volatile("ldmatrix.sync.aligned.m8n8.x4.trans.shared.b16 {%0,%1,%2,%3},[%4];" \
        : "=r"(R0),"=r"(R1),"=r"(R2),"=r"(R3) : "r"(ADDR))
#define MMAH(D,A0,A1,A2,A3,B0,B1) \
    asm volatile("mma.sync.aligned.m16n8k16.row.col.f32.f16.f16.f32 " \
        "{%0,%1,%2,%3},{%4,%5,%6,%7},{%8,%9},{%0,%1,%2,%3};" \
        : "+f"(D[0]),"+f"(D[1]),"+f"(D[2]),"+f"(D[3]) \
        : "r"(A0),"r"(A1),"r"(A2),"r"(A3),"r"(B0),"r"(B1))

// ===========================================================================
// Pre-convert: x, qkv_w, out_w -> single fp16
// ===========================================================================
#define N_QW4 (QKVN*EMBED/4)   // 786432
#define N_OW4 (EMBED*EMBED/4)  // 262144
#define N_X4  (MTOT*EMBED/4)   // 1048576

__global__ __launch_bounds__(256) void conv_kernel(
    const float* __restrict__ qkv_w, const float* __restrict__ out_w,
    const float* __restrict__ x)
{
    const int i = blockIdx.x*256 + threadIdx.x;
    if (i < N_QW4) {
        float4 v = ((const float4*)qkv_w)[i];
        ((uint2*)g_wq)[i] = make_uint2(cvth2(v.x, v.y), cvth2(v.z, v.w));
    }
    if (i < N_OW4) {
        float4 v = ((const float4*)out_w)[i];
        ((uint2*)g_wo)[i] = make_uint2(cvth2(v.x, v.y), cvth2(v.z, v.w));
    }
    if (i < N_X4) {
        float4 v = ((const float4*)x)[i];
        ((uint2*)g_x)[i] = make_uint2(cvth2(v.x, v.y), cvth2(v.z, v.w));
    }
}

// ===========================================================================
// fp16 GEMM: C[M,N] = A[M,1024] @ B[N,1024]^T (+bias)
// Single fp16. CTA 128x128, warp 32x64, K-tile 64, cp.async 2-buffer.
// Inner loop batches ALL LDSMs of a k16-step before the 16 MMAs (one exposed
// LDS latency instead of four).
// ===========================================================================
#define GEMM_BUF  36864
#define GEMM_SMEM (2*GEMM_BUF)   // 73728
#define NT_G      (EMBED/64)     // 16

__device__ __forceinline__ void gemm_stage(uint32_t sb,
    const __half* __restrict__ A, const __half* __restrict__ B,
    int rowBase, int colBase, int k0, int tid)
{
    #pragma unroll
    for (int p = 0; p < 4; p++) {
        const int idx = tid + p*256;            // 0..1023
        const int r = idx >> 3;                 // 0..127
        const int c = (idx & 7) * 8;            // elements 0..56
        const uint32_t so = (uint32_t)(r*144 + c*2);
        CP16(sb + so,         A + (size_t)(rowBase + r)*EMBED + k0 + c);
        CP16(sb + 18432 + so, B + (size_t)(colBase + r)*EMBED + k0 + c);
    }
}

template<int EPI>
__global__ __launch_bounds__(256, 2) void hmma_gemm_kernel(
    const float* __restrict__ bias, float* __restrict__ Cg)
{
    extern __shared__ __align__(16) char smc[];
    const uint32_t smb = sptr(smc);

    const __half* Ap = (EPI == 0) ? g_x  : g_a;
    const __half* Bp = (EPI == 0) ? g_wq : g_wo;

    const int tid  = threadIdx.x;
    const int lane = tid & 31;
    const int warp = tid >> 5;
    const int mw   = warp & 3;
    const int nw   = warp >> 2;
    const int g    = lane >> 2;
    const int t    = lane & 3;
    const int rowBase = blockIdx.y * 128;
    const int colBase = blockIdx.x * 128;

    float acc[2][8][4];
    #pragma unroll
    for (int i = 0; i < 2; i++)
        #pragma unroll
        for (int j = 0; j < 8; j++)
            #pragma unroll
            for (int c = 0; c < 4; c++) acc[i][j][c] = 0.f;

    gemm_stage(smb, Ap, Bp, rowBase, colBase, 0, tid);
    CP_COMMIT();

    for (int kt = 0; kt < NT_G; kt++) {
        CP_WAIT0();
        __syncthreads();          // tile kt visible; all warps done with buf kt^1
        if (kt + 1 < NT_G) {      // prefetch overlaps compute below
            gemm_stage(smb + ((kt+1)&1)*GEMM_BUF, Ap, Bp,
                       rowBase, colBase, (kt+1)*64, tid);
            CP_COMMIT();
        }
        const uint32_t bufb = smb + (kt&1)*GEMM_BUF;
        #pragma unroll
        for (int ks = 0; ks < 4; ks++) {
            const uint32_t colB = (uint32_t)((ks*16 + (lane >> 4)*8) * 2);
            // ---- batch all LDSMs for this k16 step ----
            unsigned Af[2][4], Bf[4][4];
            #pragma unroll
            for (int i = 0; i < 2; i++) {
                const uint32_t rowb = (uint32_t)((mw*32 + i*16 + (lane & 15)) * 144);
                LDSM4(Af[i][0],Af[i][1],Af[i][2],Af[i][3], bufb + rowb + colB);
            }
            #pragma unroll
            for (int bt = 0; bt < 4; bt++) {
                const uint32_t rowb = (uint32_t)((nw*64 + bt*16 + (lane & 15)) * 144);
                LDSM4(Bf[bt][0],Bf[bt][1],Bf[bt][2],Bf[bt][3], bufb + 18432 + rowb + colB);
            }
            // ---- then all 16 MMAs ----
            #pragma unroll
            for (int bt = 0; bt < 4; bt++) {
                #pragma unroll
                for (int i = 0; i < 2; i++) {
                    MMAH(acc[i][2*bt],   Af[i][0],Af[i][1],Af[i][2],Af[i][3],
                         Bf[bt][0],Bf[bt][2]);
                    MMAH(acc[i][2*bt+1], Af[i][0],Af[i][1],Af[i][2],Af[i][3],
                         Bf[bt][1],Bf[bt][3]);
                }
            }
        }
    }

    // ---- Epilogue ----
    const int cb = colBase + nw*64;     // 64-aligned -> single (head,typ) block
    if (EPI == 0) {
        const int head = cb / 192;
        const int rem  = cb - head*192;
        const int typ  = rem >> 6;
        __half* sdst = (typ == 0) ? g_qs : (typ == 1) ? g_k : g_v;
        const float scale = (typ == 0) ? 0.125f : 1.f;
        #pragma unroll
        for (int i = 0; i < 2; i++) {
            #pragma unroll
            for (int half = 0; half < 2; half++) {
                const int row = rowBase + mw*32 + i*16 + g + half*8;
                const int b_ = row >> 11, s_ = row & (SEQ - 1);
                const size_t base = (((size_t)(b_*NHEADS + head))*SEQ + s_) << 6;
                #pragma unroll
                for (int j = 0; j < 8; j++) {
                    const int d = j*8 + t*2;
                    float2 bs = *(const float2*)(bias + cb + d);
                    const float v0 = (acc[i][j][2*half]   + bs.x) * scale;
                    const float v1 = (acc[i][j][2*half+1] + bs.y) * scale;
                    *(uint32_t*)(sdst + base + d) = cvth2(v0, v1);
                }
            }
        }
    } else {
        #pragma unroll
        for (int i = 0; i < 2; i++) {
            #pragma unroll
            for (int half = 0; half < 2; half++) {
                const int row = rowBase + mw*32 + i*16 + g + half*8;
                float* dst = Cg + (size_t)row*EMBED + cb;
                #pragma unroll
                for (int j = 0; j < 8; j++) {
                    const int d = j*8 + t*2;
                    float2 bs = *(const float2*)(bias + cb + d);
                    *(float2*)(dst + d) = make_float2(acc[i][j][2*half]   + bs.x,
                                                      acc[i][j][2*half+1] + bs.y);
                }
            }
        }
    }
}

// ===========================================================================
// Flash attention: single-fp16 Q·K and P·V, batched-LDSM inner loops.
// Dyn smem: Q phase [Q@0] (pitch 144B, 18432B); then K/V:
// buf b @ b*18432: K@0 (9216B), V@9216. FLASH_SMEM = 36864.
// ===========================================================================
#define FPB        144
#define KV_BUF     18432
#define FLASH_SMEM 36864
#define NT_F       (SEQ/64)

__device__ __forceinline__ void flash_stage(uint32_t sb,
    const __half* __restrict__ K, const __half* __restrict__ V,
    int krow0, int tid)
{
    #pragma unroll
    for (int p = 0; p < 2; p++) {
        const int idx = tid + p*256;            // 0..511
        const int r = idx >> 3;                 // 0..63
        const int c = (idx & 7) * 8;            // 0..56
        const size_t go = (size_t)(krow0 + r)*HDIM + c;
        const uint32_t so = (uint32_t)(r*FPB + c*2);
        CP16(sb + so,        K + go);
        CP16(sb + 9216 + so, V + go);
    }
}

__global__ __launch_bounds__(256, 2) void flash_mma_kernel()
{
    extern __shared__ __align__(16) char smc[];
    const uint32_t smb = sptr(smc);

    const int tid  = threadIdx.x;
    const int lane = tid & 31;
    const int warp = tid >> 5;
    const int g    = lane >> 2;
    const int t    = lane & 3;
    const int h    = blockIdx.y;
    const int b    = blockIdx.z;
    const size_t base = (size_t)(b*NHEADS + h)*SEQ*HDIM;
    const size_t qbase = base + (size_t)blockIdx.x*128*HDIM;

    // --- Stage Q (pre-scaled single fp16) ---
    #pragma unroll
    for (int p = 0; p < 4; p++) {
        const int idx = tid + p*256;            // 0..1023
        const int r = idx >> 3;                 // 0..127
        const int c = (idx & 7) * 8;
        CP16(smb + (uint32_t)(r*FPB + c*2), g_qs + qbase + (size_t)r*HDIM + c);
    }
    CP_COMMIT();
    CP_WAIT0();
    __syncthreads();

    // --- Q fragments to registers ---
    unsigned Qf[4][4];
    {
        const uint32_t rowb = (uint32_t)((warp*16 + (lane & 15)) * FPB);
        const uint32_t cbb  = (uint32_t)(((lane >> 4) * 8) * 2);
        #pragma unroll
        for (int ks = 0; ks < 4; ks++) {
            LDSM4(Qf[ks][0],Qf[ks][1],Qf[ks][2],Qf[ks][3], smb + rowb + ks*32 + cbb);
        }
    }
    __syncthreads();   // smem now reusable for K/V buffers

    float Oacc[8][4];
    #pragma unroll
    for (int j = 0; j < 8; j++)
        #pragma unroll
        for (int i = 0; i < 4; i++) Oacc[j][i] = 0.f;
    float m0 = -1e30f, m1 = -1e30f, l0s = 0.f, l1s = 0.f;

    flash_stage(smb, g_k + base, g_v + base, 0, tid);
    CP_COMMIT();

    for (int kt = 0; kt < NT_F; kt++) {
        CP_WAIT0();
        __syncthreads();          // tile kt ready; all warps done with buf kt^1
        if (kt + 1 < NT_F) {
            flash_stage(smb + ((kt+1)&1)*KV_BUF, g_k + base, g_v + base,
                        (kt+1)*64, tid);
            CP_COMMIT();
        }
        const uint32_t kvb = smb + (kt&1)*KV_BUF;

        // S = (Q/8) K^T  — batch 4 LDSMs per ks, then 8 MMAs
        float S[8][4];
        #pragma unroll
        for (int j = 0; j < 8; j++)
            #pragma unroll
            for (int i = 0; i < 4; i++) S[j][i] = 0.f;

        #pragma unroll
        for (int ks = 0; ks < 4; ks++) {
            const uint32_t colb = (uint32_t)((ks*16 + (lane >> 4)*8) * 2);
            unsigned Kf[4][4];
            #pragma unroll
            for (int nb = 0; nb < 4; nb++) {
                const uint32_t rowb = (uint32_t)((nb*16 + (lane & 15)) * FPB);
                LDSM4(Kf[nb][0],Kf[nb][1],Kf[nb][2],Kf[nb][3], kvb + rowb + colb);
            }
            #pragma unroll
            for (int nb = 0; nb < 4; nb++) {
                MMAH(S[2*nb],   Qf[ks][0],Qf[ks][1],Qf[ks][2],Qf[ks][3],
                     Kf[nb][0],Kf[nb][2]);
                MMAH(S[2*nb+1], Qf[ks][0],Qf[ks][1],Qf[ks][2],Qf[ks][3],
                     Kf[nb][1],Kf[nb][3]);
            }
        }

        // Online softmax
        float mx0 = -1e30f, mx1 = -1e30f;
        #pragma unroll
        for (int j = 0; j < 8; j++) {
            mx0 = fmaxf(mx0, fmaxf(S[j][0], S[j][1]));
            mx1 = fmaxf(mx1, fmaxf(S[j][2], S[j][3]));
        }
        mx0 = fmaxf(mx0, __shfl_xor_sync(0xffffffffu, mx0, 1));
        mx0 = fmaxf(mx0, __shfl_xor_sync(0xffffffffu, mx0, 2));
        mx1 = fmaxf(mx1, __shfl_xor_sync(0xffffffffu, mx1, 1));
        mx1 = fmaxf(mx1, __shfl_xor_sync(0xffffffffu, mx1, 2));
        const float mn0 = fmaxf(m0, mx0);
        const float mn1 = fmaxf(m1, mx1);

        float sum0 = 0.f, sum1 = 0.f;
        #pragma unroll
        for (int j = 0; j < 8; j++) {
            S[j][0] = __expf(S[j][0] - mn0); sum0 += S[j][0];
            S[j][1] = __expf(S[j][1] - mn0); sum0 += S[j][1];
            S[j][2] = __expf(S[j][2] - mn1); sum1 += S[j][2];
            S[j][3] = __expf(S[j][3] - mn1); sum1 += S[j][3];
        }
        sum0 += __shfl_xor_sync(0xffffffffu, sum0, 1);
        sum0 += __shfl_xor_sync(0xffffffffu, sum0, 2);
        sum1 += __shfl_xor_sync(0xffffffffu, sum1, 1);
        sum1 += __shfl_xor_sync(0xffffffffu, sum1, 2);

        const float sc0 = __expf(m0 - mn0);
        const float sc1 = __expf(m1 - mn1);
        l0s = l0s*sc0 + sum0;
        l1s = l1s*sc1 + sum1;
        m0 = mn0; m1 = mn1;
        #pragma unroll
        for (int j = 0; j < 8; j++) {
            Oacc[j][0] *= sc0; Oacc[j][1] *= sc0;
            Oacc[j][2] *= sc1; Oacc[j][3] *= sc1;
        }

        // P single fp16
        unsigned Pf[4][4];
        #pragma unroll
        for (int ks = 0; ks < 4; ks++) {
            Pf[ks][0] = cvth2(S[2*ks  ][0], S[2*ks  ][1]);
            Pf[ks][1] = cvth2(S[2*ks  ][2], S[2*ks  ][3]);
            Pf[ks][2] = cvth2(S[2*ks+1][0], S[2*ks+1][1]);
            Pf[ks][3] = cvth2(S[2*ks+1][2], S[2*ks+1][3]);
        }

        // O += P V — batch 4 trans-LDSMs per ks, then 8 MMAs
        #pragma unroll
        for (int ks = 0; ks < 4; ks++) {
            const uint32_t rowb = (uint32_t)((ks*16 + (lane & 15)) * FPB);
            unsigned Vf[4][4];
            #pragma unroll
            for (int nb = 0; nb < 4; nb++) {
                const uint32_t colb = (uint32_t)((nb*16 + (lane >> 4)*8) * 2);
                LDSM4T(Vf[nb][0],Vf[nb][1],Vf[nb][2],Vf[nb][3],
                       kvb + 9216 + rowb + colb);
            }
            #pragma unroll
            for (int nb = 0; nb < 4; nb++) {
                MMAH(Oacc[2*nb],   Pf[ks][0],Pf[ks][1],Pf[ks][2],Pf[ks][3],
                     Vf[nb][0],Vf[nb][1]);
                MMAH(Oacc[2*nb+1], Pf[ks][0],Pf[ks][1],Pf[ks][2],Pf[ks][3],
                     Vf[nb][2],Vf[nb][3]);
            }
        }
    }

    // Epilogue: normalize + write attn single fp16 [B,S,E]
    const float inv0 = 1.f / l0s;
    const float inv1 = 1.f / l1s;
    const int q = blockIdx.x*128 + warp*16;
    const size_t rbase = ((size_t)b*SEQ + q)*EMBED + h*HDIM;
    #pragma unroll
    for (int j = 0; j < 8; j++) {
        const int col = j*8 + t*2;
        *(uint32_t*)(g_a + rbase + (size_t)g*EMBED + col) =
            cvth2(Oacc[j][0]*inv0, Oacc[j][1]*inv0);
        *(uint32_t*)(g_a + rbase + (size_t)(g+8)*EMBED + col) =
            cvth2(Oacc[j][2]*inv1, Oacc[j][3]*inv1);
    }
}

// ===========================================================================
extern "C" void kernel_launch(void* const* d_in, const int* in_sizes, int n_in,
                              void* d_out, int out_size)
{
    const float* x     = (const float*)d_in[0];
    const float* qkv_w = (const float*)d_in[1];
    const float* qkv_b = (const float*)d_in[2];
    const float* out_w = (const float*)d_in[3];
    const float* out_b = (const float*)d_in[4];
    float* out = (float*)d_out;

    cudaFuncSetAttribute(hmma_gemm_kernel<0>,
                         cudaFuncAttributeMaxDynamicSharedMemorySize, GEMM_SMEM);
    cudaFuncSetAttribute(hmma_gemm_kernel<1>,
                         cudaFuncAttributeMaxDynamicSharedMemorySize, GEMM_SMEM);
    cudaFuncSetAttribute(flash_mma_kernel,
                         cudaFuncAttributeMaxDynamicSharedMemorySize, FLASH_SMEM);

    conv_kernel<<<N_X4/256, 256>>>(qkv_w, out_w, x);
    hmma_gemm_kernel<0><<<dim3(QKVN/128, MTOT/128), 256, GEMM_SMEM>>>(qkv_b, nullptr);
    flash_mma_kernel<<<dim3(SEQ/128, NHEADS, BATCH), 256, FLASH_SMEM>>>();
    hmma_gemm_kernel<1><<<dim3(EMBED/128, MTOT/128), 256, GEMM_SMEM>>>(out_b, out);
}